// round 9
// baseline (speedup 1.0000x reference)
#include <cuda_runtime.h>
#include <cuda_fp16.h>
#include <stdint.h>

#define NN 50000
#define NNP 50048         // padded rows (391*128)
#define EE 1600000
#define YS3 256           // y stride for layer3
#define SCAN_B 49         // ceil(50000/1024)
#define MW 12             // momM warps (nodes) per block

// ---------------- device scratch (no runtime allocation allowed) ------------
__device__ __align__(16) __half g_mom[(size_t)NNP * 4224]; // 423 MB moment rows
__device__ __align__(16) __half g_y[NN * YS3];             // layer3 y (25.6 MB)
__device__ __align__(16) __half g_wm[4160 * 64];           // packed B for gemmM
__device__ __align__(16) __half g_wc[64 * 256];            // layer3 packed Wcat
__device__ __align__(16) __half g_ah[NN * 64];             // relu(ans) fp16
__device__ __align__(16) float  g_ansF[NN * 64];           // layer1 out fp32 (residual)
__device__ __align__(16) __half g_m0[(size_t)NN * 320];    // layer0 moments + x
__device__ __align__(16) __half g_wb0[320 * 64];           // layer0 packed weights
__device__ float  g_bias0[64];
__device__ float  g_bias[64];
__device__ int    g_cnt[NN + 1];
__device__ int    g_rowp[NN + 1];
__device__ int    g_cursor[NN];
__device__ int    g_bsum[SCAN_B];
__device__ int    g_boff[SCAN_B + 1];
__device__ int    g_sjk[EE];                 // j | (kb<<20)
__device__ __align__(16) float4 g_sw[EE];    // 4 hat-product weights

// ---------------- mma / async helpers ----------------------------------------
__device__ __forceinline__ void ldsm4(uint32_t& r0, uint32_t& r1, uint32_t& r2,
                                      uint32_t& r3, uint32_t addr) {
    asm volatile("ldmatrix.sync.aligned.m8n8.x4.shared.b16 {%0,%1,%2,%3}, [%4];"
                 : "=r"(r0), "=r"(r1), "=r"(r2), "=r"(r3) : "r"(addr));
}
__device__ __forceinline__ void ldsm4t(uint32_t& r0, uint32_t& r1, uint32_t& r2,
                                       uint32_t& r3, uint32_t addr) {
    asm volatile("ldmatrix.sync.aligned.m8n8.x4.trans.shared.b16 {%0,%1,%2,%3}, [%4];"
                 : "=r"(r0), "=r"(r1), "=r"(r2), "=r"(r3) : "r"(addr));
}
__device__ __forceinline__ void mma16816(float* c, const uint32_t* a,
                                         uint32_t b0, uint32_t b1) {
    asm volatile(
        "mma.sync.aligned.m16n8k16.row.col.f32.f16.f16.f32 "
        "{%0,%1,%2,%3}, {%4,%5,%6,%7}, {%8,%9}, {%0,%1,%2,%3};"
        : "+f"(c[0]), "+f"(c[1]), "+f"(c[2]), "+f"(c[3])
        : "r"(a[0]), "r"(a[1]), "r"(a[2]), "r"(a[3]), "r"(b0), "r"(b1));
}
__device__ __forceinline__ void cpa16(uint32_t dst, const void* src) {
    asm volatile("cp.async.cg.shared.global [%0], [%1], 16;" :: "r"(dst), "l"(src));
}
#define CP_COMMIT() asm volatile("cp.async.commit_group;")
#define CP_WAIT1()  asm volatile("cp.async.wait_group 1;")
#define CP_WAIT0()  asm volatile("cp.async.wait_group 0;")

// ---------------- edge preprocessing ----------------------------------------
__global__ void zero_cnt_kernel() {
    int t = blockIdx.x * blockDim.x + threadIdx.x;
    if (t <= NN) g_cnt[t] = 0;
}

__global__ void hist_kernel(const int* __restrict__ ei, int E) {
    int e = blockIdx.x * blockDim.x + threadIdx.x;
    if (e < E) atomicAdd(&g_cnt[__ldg(ei + e)], 1);
}

__global__ void scan1_kernel() {
    __shared__ int sh[1024];
    int b = blockIdx.x, tid = threadIdx.x;
    int idx = b * 1024 + tid;
    int v = (idx < NN) ? g_cnt[idx] : 0;
    sh[tid] = v;
    __syncthreads();
    for (int off = 512; off > 0; off >>= 1) {
        if (tid < off) sh[tid] += sh[tid + off];
        __syncthreads();
    }
    if (tid == 0) g_bsum[b] = sh[0];
}

__global__ void scan2_kernel() {
    __shared__ int sh[64];
    int tid = threadIdx.x;
    int v = (tid < SCAN_B) ? g_bsum[tid] : 0;
    sh[tid] = v;
    __syncthreads();
    for (int off = 1; off < 64; off <<= 1) {
        int t = (tid >= off) ? sh[tid - off] : 0;
        __syncthreads();
        sh[tid] += t;
        __syncthreads();
    }
    if (tid < SCAN_B) g_boff[tid] = sh[tid] - v;
    if (tid == SCAN_B - 1) g_boff[SCAN_B] = sh[tid];
}

__global__ void scan3_kernel() {
    __shared__ int sh[1024];
    int b = blockIdx.x, tid = threadIdx.x;
    int idx = b * 1024 + tid;
    int v = (idx < NN) ? g_cnt[idx] : 0;
    int orig = v;
    sh[tid] = v;
    __syncthreads();
    for (int off = 1; off < 1024; off <<= 1) {
        int t = (tid >= off) ? sh[tid - off] : 0;
        __syncthreads();
        sh[tid] += t;
        __syncthreads();
    }
    if (idx < NN) {
        int excl = g_boff[b] + sh[tid] - orig;
        g_rowp[idx] = excl;
        g_cursor[idx] = excl;
    }
    if (b == 0 && tid == 0) g_rowp[NN] = g_boff[SCAN_B];
}

__global__ void scatter_kernel(const float* __restrict__ pos,
                               const int* __restrict__ ei,
                               const int* __restrict__ ej, int E) {
    int e = blockIdx.x * blockDim.x + threadIdx.x;
    if (e >= E) return;
    int i = __ldg(ei + e), j = __ldg(ej + e);
    const float2* p2 = (const float2*)pos;
    float2 pi = __ldg(p2 + i);
    float2 pj = __ldg(p2 + j);
    float dx = pi.x - pj.x;
    float dy = pi.y - pj.y;
    dx = fminf(1.f, fmaxf(-1.f, dx));
    dy = fminf(1.f, fmaxf(-1.f, dy));
    float m = (i != j) ? 1.f : 0.f;
    float r = sqrtf(dx * dx + dy * dy + 1e-12f);
    float u = fminf(1.f, fmaxf(-1.f, 2.f * r - 1.f));
    float v = atan2f(dy, dx) * 0.318309886183790672f;   // 1/pi
    float su = (u + 1.f) * 3.5f;
    int   iu = min(6, (int)floorf(su));
    float tu = su - (float)iu;
    float sv = (v + 1.f) * 3.5f;
    int   iv = min(6, (int)floorf(sv));
    float tv = sv - (float)iv;
    float4 w = make_float4((1.f - tu) * (1.f - tv) * m,
                           (1.f - tu) * tv * m,
                           tu * (1.f - tv) * m,
                           tu * tv * m);
    int kb = iu * 8 + iv;
    int p = atomicAdd(&g_cursor[i], 1);
    g_sjk[p] = j | (kb << 20);
    g_sw[p] = w;
}

// ---------------- layer 0: moment accumulation (Cin=4) ----------------------
__global__ void mom0_kernel(const float* __restrict__ X) {
    __shared__ float M0s[8 * 256];
    int warp = threadIdx.x >> 5, lane = threadIdx.x & 31;
    int node = blockIdx.x * 8 + warp;
    float* M = M0s + warp * 256;
    #pragma unroll
    for (int r = 0; r < 8; r++) M[r * 32 + lane] = 0.f;
    __syncwarp();
    if (node < NN) {
        int e0 = g_rowp[node], e1 = g_rowp[node + 1];
        int t = lane >> 2, c = lane & 3;
        bool act = lane < 16;
        int kadd = (t & 1) + ((t >> 1) << 3);
        for (int e = e0; e < e1; e++) {
            int jk = __ldg(g_sjk + e);
            float4 w = __ldg(&g_sw[e]);
            int j = jk & 0xFFFFF;
            int kb = jk >> 20;
            float4 xv = __ldg((const float4*)X + j);
            if (act) {
                float wt = (t == 0) ? w.x : (t == 1) ? w.y : (t == 2) ? w.z : w.w;
                float xc = (c == 0) ? xv.x : (c == 1) ? xv.y : (c == 2) ? xv.z : xv.w;
                M[(kb + kadd) * 4 + c] += wt * xc;
            }
        }
        __syncwarp();
        __half* dst = g_m0 + (size_t)node * 320;
        #pragma unroll
        for (int r = 0; r < 4; r++) {
            int idx = r * 64 + 2 * lane;
            *(__half2*)(dst + idx) = __floats2half2_rn(M[idx], M[idx + 1]);
        }
        float4 xi = __ldg((const float4*)X + node);
        __half2 hv;
        if (lane == 0)      hv = __floats2half2_rn(xi.x, xi.y);
        else if (lane == 1) hv = __floats2half2_rn(xi.z, xi.w);
        else                hv = __floats2half2_rn(0.f, 0.f);
        *(__half2*)(dst + 256 + 2 * lane) = hv;
    }
}

// ---------------- layer 0 weight pack ---------------------------------------
__global__ void pack0_kernel(const float* __restrict__ cw0,
                             const float* __restrict__ fw0,
                             const float* __restrict__ cb0,
                             const float* __restrict__ fb0) {
    int idx = blockIdx.x * blockDim.x + threadIdx.x;   // over 320*64
    if (idx >= 320 * 64) return;
    int row = idx >> 6;
    int co = idx & 63;
    float v = 0.f;
    if (row < 256) {
        int kb = row >> 2, c = row & 3;
        if (co >= 32) v = __ldg(cw0 + (size_t)(kb * 4 + c) * 32 + (co - 32));
    } else if (row < 260) {
        int c = row - 256;
        if (co < 32) v = __ldg(fw0 + (size_t)c * 32 + co);
    }
    g_wb0[row * 64 + co] = __float2half(v);
    if (idx < 64)
        g_bias0[idx] = (idx < 32) ? __ldg(fb0 + idx) : __ldg(cb0 + idx - 32);
}

// ---------------- layer 0 GEMM: ans0 = [M0|x] @ Wb0, bias, relu -> g_ah -----
#define GAST 72
__global__ void __launch_bounds__(256)
gemmA_kernel() {
    extern __shared__ __half smA[];
    __half* As = smA;                    // [128][GAST]
    __half* Bs = smA + 128 * GAST;       // [320][GAST]
    int m0 = blockIdx.x * 128;
    int tid = threadIdx.x;

    #pragma unroll
    for (int it = 0; it < 10; it++) {
        int idx = tid + it * 256;
        int row = idx >> 3;
        int c8 = idx & 7;
        uint4 v = __ldg((const uint4*)(g_wb0 + row * 64 + c8 * 8));
        *(uint4*)(Bs + row * GAST + c8 * 8) = v;
    }

    int warp = tid >> 5, lane = tid & 31;
    int wm = warp & 3, wn = warp >> 2;
    uint32_t asB = (uint32_t)__cvta_generic_to_shared(As);
    uint32_t bsB = (uint32_t)__cvta_generic_to_shared(Bs);

    float c[2][4][4];
    #pragma unroll
    for (int mi = 0; mi < 2; mi++)
        #pragma unroll
        for (int ni = 0; ni < 4; ni++)
            #pragma unroll
            for (int p = 0; p < 4; p++) c[mi][ni][p] = 0.f;

    for (int kc = 0; kc < 5; kc++) {
        __syncthreads();
        #pragma unroll
        for (int it = 0; it < 4; it++) {
            int idx = tid + it * 256;
            int row = idx >> 3;
            int c8 = idx & 7;
            uint4 v = make_uint4(0, 0, 0, 0);
            if (m0 + row < NN)
                v = __ldg((const uint4*)(g_m0 + (size_t)(m0 + row) * 320 + kc * 64 + c8 * 8));
            *(uint4*)(As + row * GAST + c8 * 8) = v;
        }
        __syncthreads();
        #pragma unroll
        for (int ks = 0; ks < 4; ks++) {
            int k0 = ks * 16;
            uint32_t a[2][4];
            #pragma unroll
            for (int mi = 0; mi < 2; mi++) {
                int row = wm * 32 + mi * 16 + (lane & 15);
                int col = k0 + ((lane >> 4) << 3);
                ldsm4(a[mi][0], a[mi][1], a[mi][2], a[mi][3],
                      asB + (row * GAST + col) * 2);
            }
            int brow = kc * 64 + k0 + (lane & 15);
            #pragma unroll
            for (int nq = 0; nq < 2; nq++) {
                int bcol = wn * 32 + nq * 16 + ((lane >> 4) << 3);
                uint32_t b0, b1, b2, b3;
                ldsm4t(b0, b1, b2, b3, bsB + (brow * GAST + bcol) * 2);
                #pragma unroll
                for (int mi = 0; mi < 2; mi++) {
                    mma16816(c[mi][nq * 2 + 0], a[mi], b0, b1);
                    mma16816(c[mi][nq * 2 + 1], a[mi], b2, b3);
                }
            }
        }
    }

    #pragma unroll
    for (int mi = 0; mi < 2; mi++) {
        #pragma unroll
        for (int ni = 0; ni < 4; ni++) {
            int row0 = m0 + wm * 32 + mi * 16 + (lane >> 2);
            int col = wn * 32 + ni * 8 + 2 * (lane & 3);
            float2 bv = *(const float2*)(g_bias0 + col);
            if (row0 < NN)
                *(__half2*)(g_ah + (size_t)row0 * 64 + col) = __floats2half2_rn(
                    fmaxf(c[mi][ni][0] + bv.x, 0.f), fmaxf(c[mi][ni][1] + bv.y, 0.f));
            int row1 = row0 + 8;
            if (row1 < NN)
                *(__half2*)(g_ah + (size_t)row1 * 64 + col) = __floats2half2_rn(
                    fmaxf(c[mi][ni][2] + bv.x, 0.f), fmaxf(c[mi][ni][3] + bv.y, 0.f));
        }
    }
}

// ---------------- packM: B for gemmM ([4160][64]), combined bias ------------
// rows 0..4095 = cw flat ([k][cin][cout] == [k*64+c][co]); rows 4096.. = fw
__global__ void packM_kernel(const float* __restrict__ CW,
                             const float* __restrict__ FW,
                             const float* __restrict__ cb,
                             const float* __restrict__ fb) {
    int idx = blockIdx.x * blockDim.x + threadIdx.x;   // over 4160*64
    if (idx >= 4160 * 64) return;
    float v = (idx < 4096 * 64) ? __ldg(CW + idx) : __ldg(FW + (idx - 4096 * 64));
    g_wm[idx] = __float2half(v);
    if (idx < 64) g_bias[idx] = __ldg(cb + idx) + __ldg(fb + idx);
}

// ---------------- momM: mom[i, row*64+c] = sum_e w_tap * a[j,c] -------------
// warp per node; smem fp32 [64 rows][64 ch]; flush fp16 + a[i] as row 64.
__global__ void __launch_bounds__(MW * 32)
momM_kernel() {
    extern __shared__ float ms[];
    int warp = threadIdx.x >> 5, lane = threadIdx.x & 31;
    int node = blockIdx.x * MW + warp;
    float* M = ms + warp * 4096;
    #pragma unroll
    for (int r = 0; r < 32; r++)
        *(float4*)(M + r * 128 + lane * 4) = make_float4(0.f, 0.f, 0.f, 0.f);
    __syncwarp();
    if (node >= NN) return;
    int e0 = g_rowp[node], e1 = g_rowp[node + 1];
    int t = lane >> 3, cg = lane & 7;
    int rowAdd = (t & 1) + ((t >> 1) << 3);

    for (int base = e0; base < e1; base += 4) {
        int n4 = min(4, e1 - base);
        uint4 v[4]; int kb4[4]; float wt4[4];
        #pragma unroll
        for (int q = 0; q < 4; q++) {
            kb4[q] = -1;
            if (q < n4) {
                int jk = __ldg(g_sjk + base + q);
                float4 w = __ldg(&g_sw[base + q]);
                int j = jk & 0xFFFFF;
                kb4[q] = jk >> 20;
                v[q] = __ldg((const uint4*)(g_ah + (size_t)j * 64) + cg);
                wt4[q] = (t == 0) ? w.x : (t == 1) ? w.y : (t == 2) ? w.z : w.w;
            }
        }
        #pragma unroll
        for (int q = 0; q < 4; q++) {
            if (kb4[q] >= 0) {
                float* row = M + ((kb4[q] + rowAdd) << 6) + (cg << 3);
                __half2* h = (__half2*)&v[q];
                float2 f0 = __half22float2(h[0]);
                float2 f1 = __half22float2(h[1]);
                float2 f2 = __half22float2(h[2]);
                float2 f3 = __half22float2(h[3]);
                float wt = wt4[q];
                float4 r0 = *(float4*)row;
                float4 r1 = *(float4*)(row + 4);
                r0.x += wt * f0.x; r0.y += wt * f0.y;
                r0.z += wt * f1.x; r0.w += wt * f1.y;
                r1.x += wt * f2.x; r1.y += wt * f2.y;
                r1.z += wt * f3.x; r1.w += wt * f3.y;
                *(float4*)row = r0;
                *(float4*)(row + 4) = r1;
            }
        }
    }
    __syncwarp();
    __half* dst = g_mom + (size_t)node * 4224;
    #pragma unroll
    for (int it = 0; it < 16; it++) {
        int idx = it * 256 + lane * 8;
        float4 a = *(float4*)(M + idx);
        float4 b = *(float4*)(M + idx + 4);
        __half2 h0 = __floats2half2_rn(a.x, a.y);
        __half2 h1 = __floats2half2_rn(a.z, a.w);
        __half2 h2 = __floats2half2_rn(b.x, b.y);
        __half2 h3 = __floats2half2_rn(b.z, b.w);
        uint4 pkt;
        pkt.x = *(uint32_t*)&h0; pkt.y = *(uint32_t*)&h1;
        pkt.z = *(uint32_t*)&h2; pkt.w = *(uint32_t*)&h3;
        *(uint4*)(dst + idx) = pkt;
    }
    if (lane < 8)
        *(uint4*)(dst + 4096 + lane * 8) =
            *(const uint4*)(g_ah + (size_t)node * 64 + lane * 8);
}

// ---------------- gemmM: out = mom @ Wm (K=4160), bias/relu/resid fused -----
#define MAST 72
#define MBST 72
#define GM_SMEM ((2 * 128 * MAST + 2 * 64 * MBST) * 2)   // 55296 B

template <bool RES, bool WF32>
__global__ void __launch_bounds__(256)
gemmM_kernel(const float* __restrict__ resid, float* __restrict__ outF) {
    extern __shared__ __half sg[];
    __half* Abuf[2] = {sg, sg + 128 * MAST};
    __half* Bbuf[2] = {sg + 2 * 128 * MAST, sg + 2 * 128 * MAST + 64 * MBST};
    int m0 = blockIdx.x * 128;
    int tid = threadIdx.x;
    int warp = tid >> 5, lane = tid & 31;

    auto loadChunk = [&](int buf, int kc) {
        uint32_t ab = (uint32_t)__cvta_generic_to_shared(Abuf[buf]);
        #pragma unroll
        for (int it = 0; it < 4; it++) {
            int idx = tid + it * 256;          // 1024 x 16B
            int row = idx >> 3, c8 = idx & 7;
            cpa16(ab + (row * MAST + c8 * 8) * 2,
                  g_mom + (size_t)(m0 + row) * 4224 + kc * 64 + c8 * 8);
        }
        uint32_t bb = (uint32_t)__cvta_generic_to_shared(Bbuf[buf]);
        #pragma unroll
        for (int it = 0; it < 2; it++) {
            int idx = tid + it * 256;          // 512 x 16B
            int row = idx >> 3, c8 = idx & 7;
            cpa16(bb + (row * MBST + c8 * 8) * 2,
                  g_wm + (size_t)(kc * 64 + row) * 64 + c8 * 8);
        }
        CP_COMMIT();
    };

    float c[8][4];
    #pragma unroll
    for (int ni = 0; ni < 8; ni++)
        #pragma unroll
        for (int p = 0; p < 4; p++) c[ni][p] = 0.f;

    loadChunk(0, 0);
    for (int kc = 0; kc < 65; kc++) {
        int buf = kc & 1;
        if (kc < 64) loadChunk(buf ^ 1, kc + 1);
        if (kc < 64) { CP_WAIT1(); } else { CP_WAIT0(); }
        __syncthreads();
        uint32_t ab = (uint32_t)__cvta_generic_to_shared(Abuf[buf]);
        uint32_t bb = (uint32_t)__cvta_generic_to_shared(Bbuf[buf]);
        #pragma unroll
        for (int ks = 0; ks < 4; ks++) {
            int k0 = ks * 16;
            uint32_t a[4];
            ldsm4(a[0], a[1], a[2], a[3],
                  ab + ((warp * 16 + (lane & 15)) * MAST + k0 + ((lane >> 4) << 3)) * 2);
            #pragma unroll
            for (int nq = 0; nq < 4; nq++) {
                uint32_t b0, b1, b2, b3;
                ldsm4t(b0, b1, b2, b3,
                       bb + ((k0 + (lane & 15)) * MBST + nq * 16 + ((lane >> 4) << 3)) * 2);
                mma16816(c[nq * 2 + 0], a, b0, b1);
                mma16816(c[nq * 2 + 1], a, b2, b3);
            }
        }
        __syncthreads();
    }

    // epilogue: bias (+resid) -> g_ah relu fp16 (+outF fp32)
    int r0 = m0 + warp * 16 + (lane >> 2);
    int r1 = r0 + 8;
    #pragma unroll
    for (int ni = 0; ni < 8; ni++) {
        int col = ni * 8 + 2 * (lane & 3);
        float2 bv = *(const float2*)(g_bias + col);
        float o0 = c[ni][0] + bv.x, o1 = c[ni][1] + bv.y;
        float o2 = c[ni][2] + bv.x, o3 = c[ni][3] + bv.y;
        if (RES) {
            if (r0 < NN) {
                float2 rv = *(const float2*)(resid + (size_t)r0 * 64 + col);
                o0 += rv.x; o1 += rv.y;
            }
            if (r1 < NN) {
                float2 rv = *(const float2*)(resid + (size_t)r1 * 64 + col);
                o2 += rv.x; o3 += rv.y;
            }
        }
        if (r0 < NN) {
            if (WF32) *(float2*)(outF + (size_t)r0 * 64 + col) = make_float2(o0, o1);
            *(__half2*)(g_ah + (size_t)r0 * 64 + col) =
                __floats2half2_rn(fmaxf(o0, 0.f), fmaxf(o1, 0.f));
        }
        if (r1 < NN) {
            if (WF32) *(float2*)(outF + (size_t)r1 * 64 + col) = make_float2(o2, o3);
            *(__half2*)(g_ah + (size_t)r1 * 64 + col) =
                __floats2half2_rn(fmaxf(o2, 0.f), fmaxf(o3, 0.f));
        }
    }
}

// ---------------- layer3 weight pack: g_wc[k][col], col = kk*2+co | fw ------
__global__ void pack_kernel(const float* __restrict__ CW,
                            const float* __restrict__ FW,
                            int ncols, int ncolsPad, int coutShift, int coutMask) {
    int idx = blockIdx.x * blockDim.x + threadIdx.x;   // over 64*ncolsPad
    if (idx >= 64 * ncolsPad) return;
    int k = idx / ncolsPad;
    int col = idx - k * ncolsPad;
    int cout = 1 << coutShift;
    int kcoutTot = 64 << coutShift;
    float w = 0.f;
    if (col < ncols) {
        if (col < kcoutTot) {
            int kk = col >> coutShift;
            int co = col & coutMask;
            w = __ldg(CW + (size_t)(kk * 64 + k) * cout + co);
        } else {
            w = __ldg(FW + (size_t)k * cout + (col - kcoutTot));
        }
    }
    g_wc[k * ncolsPad + col] = __float2half(w);
}

// ---------------- layer3 GEMM: y3 = ah @ Wcat3 (tensor cores) ---------------
#define AST 72
#define BST 136
#define CST 136
#define SMEMB ((128 * AST + 64 * BST) * 2)   // 35840 B

__global__ void __launch_bounds__(256, 2)
gemm64_kernel(int ystride) {
    extern __shared__ __half sm[];
    __half* As = sm;                 // [128][AST]
    __half* Bs = sm + 128 * AST;     // [64][BST]
    int n0 = blockIdx.x * 128;
    int m0 = blockIdx.y * 128;
    int tid = threadIdx.x;

    #pragma unroll
    for (int it = 0; it < 4; it++) {
        int idx = tid + it * 256;
        int row = idx >> 3;
        int c8 = idx & 7;
        uint4 v = make_uint4(0, 0, 0, 0);
        if (m0 + row < NN)
            v = __ldg((const uint4*)(g_ah + (size_t)(m0 + row) * 64 + c8 * 8));
        *(uint4*)(As + row * AST + c8 * 8) = v;
    }
    #pragma unroll
    for (int it = 0; it < 4; it++) {
        int idx = tid + it * 256;
        int row = idx >> 4;
        int c8 = idx & 15;
        uint4 v = __ldg((const uint4*)(g_wc + row * 256 + n0 + c8 * 8));
        *(uint4*)(Bs + row * BST + c8 * 8) = v;
    }
    __syncthreads();

    int warp = tid >> 5, lane = tid & 31;
    int wm = warp & 3;
    int wn = warp >> 2;
    uint32_t asBase = (uint32_t)__cvta_generic_to_shared(As);
    uint32_t bsBase = (uint32_t)__cvta_generic_to_shared(Bs);

    float c[2][8][4];
    #pragma unroll
    for (int mi = 0; mi < 2; mi++)
        #pragma unroll
        for (int ni = 0; ni < 8; ni++)
            #pragma unroll
            for (int p = 0; p < 4; p++) c[mi][ni][p] = 0.f;

    #pragma unroll
    for (int ks = 0; ks < 4; ks++) {
        int k0 = ks * 16;
        uint32_t a[2][4];
        #pragma unroll
        for (int mi = 0; mi < 2; mi++) {
            int row = wm * 32 + mi * 16 + (lane & 15);
            int col = k0 + ((lane >> 4) << 3);
            ldsm4(a[mi][0], a[mi][1], a[mi][2], a[mi][3],
                  asBase + (row * AST + col) * 2);
        }
        #pragma unroll
        for (int nq = 0; nq < 4; nq++) {
            int row = k0 + (lane & 15);
            int col = wn * 64 + nq * 16 + ((lane >> 4) << 3);
            uint32_t b0, b1, b2, b3;
            ldsm4t(b0, b1, b2, b3, bsBase + (row * BST + col) * 2);
            #pragma unroll
            for (int mi = 0; mi < 2; mi++) {
                mma16816(c[mi][nq * 2 + 0], a[mi], b0, b1);
                mma16816(c[mi][nq * 2 + 1], a[mi], b2, b3);
            }
        }
    }

    __syncthreads();
    __half* Cs = sm;                      // [128][CST]
    #pragma unroll
    for (int mi = 0; mi < 2; mi++) {
        #pragma unroll
        for (int ni = 0; ni < 8; ni++) {
            int r0 = wm * 32 + mi * 16 + (lane >> 2);
            int col = wn * 64 + ni * 8 + 2 * (lane & 3);
            *(__half2*)(Cs + r0 * CST + col) =
                __floats2half2_rn(c[mi][ni][0], c[mi][ni][1]);
            *(__half2*)(Cs + (r0 + 8) * CST + col) =
                __floats2half2_rn(c[mi][ni][2], c[mi][ni][3]);
        }
    }
    __syncthreads();
    #pragma unroll
    for (int p = 0; p < 4; p++) {
        int row = p * 32 + (tid >> 3);
        int gr = m0 + row;
        if (gr < NN) {
            int col = (tid & 7) * 16;
            uint4 v0 = *(const uint4*)(Cs + row * CST + col);
            uint4 v1 = *(const uint4*)(Cs + row * CST + col + 8);
            __half* dst = g_y + (size_t)gr * ystride + n0 + col;
            *(uint4*)(dst) = v0;
            *(uint4*)(dst + 8) = v1;
        }
    }
}

// ---------------- final gather (Cout = 2) + /128 ----------------------------
__global__ void gatherF_kernel(const float* __restrict__ cb3,
                               const float* __restrict__ fb3,
                               float* __restrict__ out) {
    int warpId = (blockIdx.x * blockDim.x + threadIdx.x) >> 5;
    int lane = threadIdx.x & 31;
    if (warpId >= NN) return;
    int i = warpId;
    int e0 = g_rowp[i], e1 = g_rowp[i + 1];
    float accx = 0.f, accy = 0.f;
    for (int e = e0 + lane; e < e1; e += 32) {
        int jk = __ldg(g_sjk + e);
        float4 w = __ldg(&g_sw[e]);
        int j = jk & 0xFFFFF;
        int kb = jk >> 20;
        const __half2* r = (const __half2*)(g_y + (size_t)j * YS3 + kb * 2);
        float2 f0 = __half22float2(__ldg(r));
        float2 f1 = __half22float2(__ldg(r + 1));
        float2 f2 = __half22float2(__ldg(r + 8));
        float2 f3 = __half22float2(__ldg(r + 9));
        accx += w.x * f0.x + w.y * f1.x + w.z * f2.x + w.w * f3.x;
        accy += w.x * f0.y + w.y * f1.y + w.z * f2.y + w.w * f3.y;
    }
    #pragma unroll
    for (int off = 16; off > 0; off >>= 1) {
        accx += __shfl_down_sync(0xFFFFFFFFu, accx, off);
        accy += __shfl_down_sync(0xFFFFFFFFu, accy, off);
    }
    if (lane == 0) {
        float2 ds = __half22float2(*(const __half2*)(g_y + (size_t)i * YS3 + 128));
        out[2 * i]     = (accx + ds.x + cb3[0] + fb3[0]) * (1.f / 128.f);
        out[2 * i + 1] = (accy + ds.y + cb3[1] + fb3[1]) * (1.f / 128.f);
    }
}

// ---------------- launch ----------------------------------------------------
extern "C" void kernel_launch(void* const* d_in, const int* in_sizes, int n_in,
                              void* d_out, int out_size) {
    const float* pos  = (const float*)d_in[0];
    const float* feat = (const float*)d_in[1];
    const int*   ei   = (const int*)d_in[2];
    const int*   ej   = (const int*)d_in[3];
    const float* cw0 = (const float*)d_in[4];
    const float* cb0 = (const float*)d_in[5];
    const float* fw0 = (const float*)d_in[6];
    const float* fb0 = (const float*)d_in[7];
    const float* cw1 = (const float*)d_in[8];
    const float* cb1 = (const float*)d_in[9];
    const float* fw1 = (const float*)d_in[10];
    const float* fb1 = (const float*)d_in[11];
    const float* cw2 = (const float*)d_in[12];
    const float* cb2 = (const float*)d_in[13];
    const float* fw2 = (const float*)d_in[14];
    const float* fb2 = (const float*)d_in[15];
    const float* cw3 = (const float*)d_in[16];
    const float* cb3 = (const float*)d_in[17];
    const float* fw3 = (const float*)d_in[18];
    const float* fb3 = (const float*)d_in[19];
    float* out = (float*)d_out;
    int E = in_sizes[2];

    const int SMEMA = (128 * GAST + 320 * GAST) * 2;   // 64512 B
    const int SMEMM = MW * 4096 * 4;                   // 196608 B
    cudaFuncSetAttribute(gemmA_kernel,
                         cudaFuncAttributeMaxDynamicSharedMemorySize, SMEMA);
    cudaFuncSetAttribute(momM_kernel,
                         cudaFuncAttributeMaxDynamicSharedMemorySize, SMEMM);
    cudaFuncSetAttribute(gemmM_kernel<false, true>,
                         cudaFuncAttributeMaxDynamicSharedMemorySize, GM_SMEM);
    cudaFuncSetAttribute(gemmM_kernel<true, false>,
                         cudaFuncAttributeMaxDynamicSharedMemorySize, GM_SMEM);
    cudaFuncSetAttribute(gemm64_kernel,
                         cudaFuncAttributeMaxDynamicSharedMemorySize, SMEMB);

    float* aF; cudaGetSymbolAddress((void**)&aF, g_ansF);

    // edge counting sort
    zero_cnt_kernel<<<(NN + 256) / 256, 256>>>();
    hist_kernel<<<(E + 255) / 256, 256>>>(ei, E);
    scan1_kernel<<<SCAN_B, 1024>>>();
    scan2_kernel<<<1, 64>>>();
    scan3_kernel<<<SCAN_B, 1024>>>();
    scatter_kernel<<<(E + 255) / 256, 256>>>(pos, ei, ej, E);

    // layer 0 (moment formulation, Cin=4)
    pack0_kernel<<<(320 * 64 + 255) / 256, 256>>>(cw0, fw0, cb0, fb0);
    mom0_kernel<<<NN / 8, 256>>>(feat);
    gemmA_kernel<<<391, 256, SMEMA>>>();

    // layer 1 (moment formulation, Cin=64)
    packM_kernel<<<(4160 * 64 + 255) / 256, 256>>>(cw1, fw1, cb1, fb1);
    momM_kernel<<<(NN + MW - 1) / MW, MW * 32, SMEMM>>>();
    gemmM_kernel<false, true><<<391, 256, GM_SMEM>>>(nullptr, aF);

    // layer 2 (residual = ansF)
    packM_kernel<<<(4160 * 64 + 255) / 256, 256>>>(cw2, fw2, cb2, fb2);
    momM_kernel<<<(NN + MW - 1) / MW, MW * 32, SMEMM>>>();
    gemmM_kernel<true, false><<<391, 256, GM_SMEM>>>(aF, nullptr);

    // layer 3 (y + gather, small)
    pack_kernel<<<(64 * 256 + 255) / 256, 256>>>(cw3, fw3, 130, 256, 1, 1);
    gemm64_kernel<<<dim3(2, 391), 256, SMEMB>>>(YS3);
    gatherF_kernel<<<(NN * 32 + 255) / 256, 256>>>(cb3, fb3, out);
}

// round 10
// speedup vs baseline: 2.0798x; 2.0798x over previous
#include <cuda_runtime.h>
#include <cuda_fp16.h>
#include <stdint.h>

#define NN 50000
#define EE 1600000
#define YS1 4224          // padded y stride (halves) for 64->64 layers (33*128)
#define YS3 256           // y stride for layer3
#define NPAD 4224         // packed-weight column pad (layers 1/2)
#define SCAN_B 49         // ceil(50000/1024)

// ---------------- device scratch (no runtime allocation allowed) ------------
__device__ __align__(16) __half g_y[(size_t)NN * YS1];   // 422 MB
__device__ __align__(16) __half g_wc[64 * NPAD];         // packed fp16 Wcat (layers 1-3)
__device__ __align__(16) __half g_ah[NN * 64];           // relu(ans) fp16 (GEMM A)
__device__ __align__(16) float  g_ansF[NN * 64];         // layer1 out fp32 (residual)
__device__ __align__(16) __half g_m0[(size_t)NN * 320];  // layer0 moments + x, fp16
__device__ __align__(16) __half g_wb0[320 * 64];         // layer0 packed weights
__device__ float  g_bias0[64];
__device__ float  g_bias[64];
__device__ int    g_cnt[NN + 1];
__device__ int    g_rowp[NN + 1];
__device__ int    g_rank[EE];
__device__ int    g_bsum[SCAN_B];
__device__ int    g_boff[SCAN_B + 1];
__device__ int    g_sjk[EE];                 // j | (kb<<20)
__device__ __align__(16) float4 g_sw[EE];    // 4 hat-product weights

// ---------------- mma helpers ------------------------------------------------
__device__ __forceinline__ void ldsm4(uint32_t& r0, uint32_t& r1, uint32_t& r2,
                                      uint32_t& r3, uint32_t addr) {
    asm volatile("ldmatrix.sync.aligned.m8n8.x4.shared.b16 {%0,%1,%2,%3}, [%4];"
                 : "=r"(r0), "=r"(r1), "=r"(r2), "=r"(r3) : "r"(addr));
}
__device__ __forceinline__ void ldsm4t(uint32_t& r0, uint32_t& r1, uint32_t& r2,
                                       uint32_t& r3, uint32_t addr) {
    asm volatile("ldmatrix.sync.aligned.m8n8.x4.trans.shared.b16 {%0,%1,%2,%3}, [%4];"
                 : "=r"(r0), "=r"(r1), "=r"(r2), "=r"(r3) : "r"(addr));
}
__device__ __forceinline__ void mma16816(float* c, const uint32_t* a,
                                         uint32_t b0, uint32_t b1) {
    asm volatile(
        "mma.sync.aligned.m16n8k16.row.col.f32.f16.f16.f32 "
        "{%0,%1,%2,%3}, {%4,%5,%6,%7}, {%8,%9}, {%0,%1,%2,%3};"
        : "+f"(c[0]), "+f"(c[1]), "+f"(c[2]), "+f"(c[3])
        : "r"(a[0]), "r"(a[1]), "r"(a[2]), "r"(a[3]), "r"(b0), "r"(b1));
}

// ---------------- edge preprocessing ----------------------------------------
__global__ void zero_cnt_kernel() {
    int t = blockIdx.x * blockDim.x + threadIdx.x;
    if (t <= NN) g_cnt[t] = 0;
}

// hist + rank in one atomic pass
__global__ void hist_kernel(const int* __restrict__ ei, int E) {
    int e = blockIdx.x * blockDim.x + threadIdx.x;
    if (e < E) g_rank[e] = atomicAdd(&g_cnt[__ldg(ei + e)], 1);
}

__global__ void scan1_kernel() {
    __shared__ int sh[1024];
    int b = blockIdx.x, tid = threadIdx.x;
    int idx = b * 1024 + tid;
    int v = (idx < NN) ? g_cnt[idx] : 0;
    sh[tid] = v;
    __syncthreads();
    for (int off = 512; off > 0; off >>= 1) {
        if (tid < off) sh[tid] += sh[tid + off];
        __syncthreads();
    }
    if (tid == 0) g_bsum[b] = sh[0];
}

__global__ void scan2_kernel() {
    __shared__ int sh[64];
    int tid = threadIdx.x;
    int v = (tid < SCAN_B) ? g_bsum[tid] : 0;
    sh[tid] = v;
    __syncthreads();
    for (int off = 1; off < 64; off <<= 1) {
        int t = (tid >= off) ? sh[tid - off] : 0;
        __syncthreads();
        sh[tid] += t;
        __syncthreads();
    }
    if (tid < SCAN_B) g_boff[tid] = sh[tid] - v;
    if (tid == SCAN_B - 1) g_boff[SCAN_B] = sh[tid];
}

__global__ void scan3_kernel() {
    __shared__ int sh[1024];
    int b = blockIdx.x, tid = threadIdx.x;
    int idx = b * 1024 + tid;
    int v = (idx < NN) ? g_cnt[idx] : 0;
    int orig = v;
    sh[tid] = v;
    __syncthreads();
    for (int off = 1; off < 1024; off <<= 1) {
        int t = (tid >= off) ? sh[tid - off] : 0;
        __syncthreads();
        sh[tid] += t;
        __syncthreads();
    }
    if (idx < NN)
        g_rowp[idx] = g_boff[b] + sh[tid] - orig;
    if (b == 0 && tid == 0) g_rowp[NN] = g_boff[SCAN_B];
}

__global__ void scatter_kernel(const float* __restrict__ pos,
                               const int* __restrict__ ei,
                               const int* __restrict__ ej, int E) {
    int e = blockIdx.x * blockDim.x + threadIdx.x;
    if (e >= E) return;
    int i = __ldg(ei + e), j = __ldg(ej + e);
    const float2* p2 = (const float2*)pos;
    float2 pi = __ldg(p2 + i);
    float2 pj = __ldg(p2 + j);
    float dx = pi.x - pj.x;
    float dy = pi.y - pj.y;
    dx = fminf(1.f, fmaxf(-1.f, dx));
    dy = fminf(1.f, fmaxf(-1.f, dy));
    float m = (i != j) ? 1.f : 0.f;
    float r = sqrtf(dx * dx + dy * dy + 1e-12f);
    float u = fminf(1.f, fmaxf(-1.f, 2.f * r - 1.f));
    float v = atan2f(dy, dx) * 0.318309886183790672f;   // 1/pi
    float su = (u + 1.f) * 3.5f;
    int   iu = min(6, (int)floorf(su));
    float tu = su - (float)iu;
    float sv = (v + 1.f) * 3.5f;
    int   iv = min(6, (int)floorf(sv));
    float tv = sv - (float)iv;
    float4 w = make_float4((1.f - tu) * (1.f - tv) * m,
                           (1.f - tu) * tv * m,
                           tu * (1.f - tv) * m,
                           tu * tv * m);
    int kb = iu * 8 + iv;
    int p = g_rowp[i] + g_rank[e];
    g_sjk[p] = j | (kb << 20);
    g_sw[p] = w;
}

// ---------------- layer 0: moment accumulation (Cin=4) ----------------------
__global__ void mom0_kernel(const float* __restrict__ X) {
    __shared__ float M0s[8 * 256];
    int warp = threadIdx.x >> 5, lane = threadIdx.x & 31;
    int node = blockIdx.x * 8 + warp;
    float* M = M0s + warp * 256;
    #pragma unroll
    for (int r = 0; r < 8; r++) M[r * 32 + lane] = 0.f;
    __syncwarp();
    if (node < NN) {
        int e0 = g_rowp[node], e1 = g_rowp[node + 1];
        int t = lane >> 2, c = lane & 3;
        bool act = lane < 16;
        int kadd = (t & 1) + ((t >> 1) << 3);
        for (int e = e0; e < e1; e++) {
            int jk = __ldg(g_sjk + e);
            float4 w = __ldg(&g_sw[e]);
            int j = jk & 0xFFFFF;
            int kb = jk >> 20;
            float4 xv = __ldg((const float4*)X + j);
            if (act) {
                float wt = (t == 0) ? w.x : (t == 1) ? w.y : (t == 2) ? w.z : w.w;
                float xc = (c == 0) ? xv.x : (c == 1) ? xv.y : (c == 2) ? xv.z : xv.w;
                M[(kb + kadd) * 4 + c] += wt * xc;
            }
        }
        __syncwarp();
        __half* dst = g_m0 + (size_t)node * 320;
        #pragma unroll
        for (int r = 0; r < 4; r++) {
            int idx = r * 64 + 2 * lane;
            *(__half2*)(dst + idx) = __floats2half2_rn(M[idx], M[idx + 1]);
        }
        float4 xi = __ldg((const float4*)X + node);
        __half2 hv;
        if (lane == 0)      hv = __floats2half2_rn(xi.x, xi.y);
        else if (lane == 1) hv = __floats2half2_rn(xi.z, xi.w);
        else                hv = __floats2half2_rn(0.f, 0.f);
        *(__half2*)(dst + 256 + 2 * lane) = hv;
    }
}

// ---------------- layer 0 weight pack ---------------------------------------
__global__ void pack0_kernel(const float* __restrict__ cw0,
                             const float* __restrict__ fw0,
                             const float* __restrict__ cb0,
                             const float* __restrict__ fb0) {
    int idx = blockIdx.x * blockDim.x + threadIdx.x;   // over 320*64
    if (idx >= 320 * 64) return;
    int row = idx >> 6;
    int co = idx & 63;
    float v = 0.f;
    if (row < 256) {
        int kb = row >> 2, c = row & 3;
        if (co >= 32) v = __ldg(cw0 + (size_t)(kb * 4 + c) * 32 + (co - 32));
    } else if (row < 260) {
        int c = row - 256;
        if (co < 32) v = __ldg(fw0 + (size_t)c * 32 + co);
    }
    g_wb0[row * 64 + co] = __float2half(v);
    if (idx < 64)
        g_bias0[idx] = (idx < 32) ? __ldg(fb0 + idx) : __ldg(cb0 + idx - 32);
}

// ---------------- layer 0 GEMM: ans0 = [M0|x] @ Wb0, bias, relu -> g_ah -----
#define GAST 72
__global__ void __launch_bounds__(256)
gemmA_kernel() {
    extern __shared__ __half smA[];
    __half* As = smA;                    // [128][GAST]
    __half* Bs = smA + 128 * GAST;       // [320][GAST]
    int m0 = blockIdx.x * 128;
    int tid = threadIdx.x;

    #pragma unroll
    for (int it = 0; it < 10; it++) {
        int idx = tid + it * 256;
        int row = idx >> 3;
        int c8 = idx & 7;
        uint4 v = __ldg((const uint4*)(g_wb0 + row * 64 + c8 * 8));
        *(uint4*)(Bs + row * GAST + c8 * 8) = v;
    }

    int warp = tid >> 5, lane = tid & 31;
    int wm = warp & 3, wn = warp >> 2;
    uint32_t asB = (uint32_t)__cvta_generic_to_shared(As);
    uint32_t bsB = (uint32_t)__cvta_generic_to_shared(Bs);

    float c[2][4][4];
    #pragma unroll
    for (int mi = 0; mi < 2; mi++)
        #pragma unroll
        for (int ni = 0; ni < 4; ni++)
            #pragma unroll
            for (int p = 0; p < 4; p++) c[mi][ni][p] = 0.f;

    for (int kc = 0; kc < 5; kc++) {
        __syncthreads();
        #pragma unroll
        for (int it = 0; it < 4; it++) {
            int idx = tid + it * 256;
            int row = idx >> 3;
            int c8 = idx & 7;
            uint4 v = make_uint4(0, 0, 0, 0);
            if (m0 + row < NN)
                v = __ldg((const uint4*)(g_m0 + (size_t)(m0 + row) * 320 + kc * 64 + c8 * 8));
            *(uint4*)(As + row * GAST + c8 * 8) = v;
        }
        __syncthreads();
        #pragma unroll
        for (int ks = 0; ks < 4; ks++) {
            int k0 = ks * 16;
            uint32_t a[2][4];
            #pragma unroll
            for (int mi = 0; mi < 2; mi++) {
                int row = wm * 32 + mi * 16 + (lane & 15);
                int col = k0 + ((lane >> 4) << 3);
                ldsm4(a[mi][0], a[mi][1], a[mi][2], a[mi][3],
                      asB + (row * GAST + col) * 2);
            }
            int brow = kc * 64 + k0 + (lane & 15);
            #pragma unroll
            for (int nq = 0; nq < 2; nq++) {
                int bcol = wn * 32 + nq * 16 + ((lane >> 4) << 3);
                uint32_t b0, b1, b2, b3;
                ldsm4t(b0, b1, b2, b3, bsB + (brow * GAST + bcol) * 2);
                #pragma unroll
                for (int mi = 0; mi < 2; mi++) {
                    mma16816(c[mi][nq * 2 + 0], a[mi], b0, b1);
                    mma16816(c[mi][nq * 2 + 1], a[mi], b2, b3);
                }
            }
        }
    }

    #pragma unroll
    for (int mi = 0; mi < 2; mi++) {
        #pragma unroll
        for (int ni = 0; ni < 4; ni++) {
            int row0 = m0 + wm * 32 + mi * 16 + (lane >> 2);
            int col = wn * 32 + ni * 8 + 2 * (lane & 3);
            float2 bv = *(const float2*)(g_bias0 + col);
            if (row0 < NN)
                *(__half2*)(g_ah + (size_t)row0 * 64 + col) = __floats2half2_rn(
                    fmaxf(c[mi][ni][0] + bv.x, 0.f), fmaxf(c[mi][ni][1] + bv.y, 0.f));
            int row1 = row0 + 8;
            if (row1 < NN)
                *(__half2*)(g_ah + (size_t)row1 * 64 + col) = __floats2half2_rn(
                    fmaxf(c[mi][ni][2] + bv.x, 0.f), fmaxf(c[mi][ni][3] + bv.y, 0.f));
        }
    }
}

// ---------------- weight pack (layers 1-3): g_wc[k, col] = fp16 Wcat --------
__global__ void pack_kernel(const float* __restrict__ CW,
                            const float* __restrict__ FW,
                            const float* __restrict__ cb,
                            const float* __restrict__ fb,
                            int ncols, int ncolsPad, int coutShift, int coutMask,
                            int biasN) {
    int idx = blockIdx.x * blockDim.x + threadIdx.x;   // over 64*ncolsPad
    if (idx >= 64 * ncolsPad) return;
    int k = idx / ncolsPad;
    int col = idx - k * ncolsPad;
    int cout = 1 << coutShift;
    int kcoutTot = 64 << coutShift;
    float w = 0.f;
    if (col < ncols) {
        if (col < kcoutTot) {
            int kk = col >> coutShift;
            int co = col & coutMask;
            w = __ldg(CW + (size_t)(kk * 64 + k) * cout + co);
        } else {
            w = __ldg(FW + (size_t)k * cout + (col - kcoutTot));
        }
    }
    g_wc[k * NPAD + col] = __float2half(w);
    if (idx < biasN) g_bias[idx] = __ldg(cb + idx) + __ldg(fb + idx);
}

// ---------------- main GEMM (tensor cores): Y = Ah @ Wcat -------------------
#define AST 72    // As row stride (halves)
#define BST 136   // Bs row stride (halves)
#define CST 136   // C staging row stride (halves)
#define SMEMB ((128 * AST + 64 * BST) * 2)   // 35840 B

__global__ void __launch_bounds__(256, 2)
gemm64_kernel(int ystride) {
    extern __shared__ __half sm[];
    __half* As = sm;                 // [128][AST]
    __half* Bs = sm + 128 * AST;     // [64][BST]
    int n0 = blockIdx.x * 128;
    int m0 = blockIdx.y * 128;
    int tid = threadIdx.x;

    #pragma unroll
    for (int it = 0; it < 4; it++) {
        int idx = tid + it * 256;
        int row = idx >> 3;
        int c8 = idx & 7;
        uint4 v = make_uint4(0, 0, 0, 0);
        if (m0 + row < NN)
            v = __ldg((const uint4*)(g_ah + (size_t)(m0 + row) * 64 + c8 * 8));
        *(uint4*)(As + row * AST + c8 * 8) = v;
    }
    #pragma unroll
    for (int it = 0; it < 4; it++) {
        int idx = tid + it * 256;
        int row = idx >> 4;
        int c8 = idx & 15;
        uint4 v = __ldg((const uint4*)(g_wc + row * NPAD + n0 + c8 * 8));
        *(uint4*)(Bs + row * BST + c8 * 8) = v;
    }
    __syncthreads();

    int warp = tid >> 5, lane = tid & 31;
    int wm = warp & 3;
    int wn = warp >> 2;
    uint32_t asBase = (uint32_t)__cvta_generic_to_shared(As);
    uint32_t bsBase = (uint32_t)__cvta_generic_to_shared(Bs);

    float c[2][8][4];
    #pragma unroll
    for (int mi = 0; mi < 2; mi++)
        #pragma unroll
        for (int ni = 0; ni < 8; ni++)
            #pragma unroll
            for (int p = 0; p < 4; p++) c[mi][ni][p] = 0.f;

    #pragma unroll
    for (int ks = 0; ks < 4; ks++) {
        int k0 = ks * 16;
        uint32_t a[2][4];
        #pragma unroll
        for (int mi = 0; mi < 2; mi++) {
            int row = wm * 32 + mi * 16 + (lane & 15);
            int col = k0 + ((lane >> 4) << 3);
            ldsm4(a[mi][0], a[mi][1], a[mi][2], a[mi][3],
                  asBase + (row * AST + col) * 2);
        }
        #pragma unroll
        for (int nq = 0; nq < 4; nq++) {
            int row = k0 + (lane & 15);
            int col = wn * 64 + nq * 16 + ((lane >> 4) << 3);
            uint32_t b0, b1, b2, b3;
            ldsm4t(b0, b1, b2, b3, bsBase + (row * BST + col) * 2);
            #pragma unroll
            for (int mi = 0; mi < 2; mi++) {
                mma16816(c[mi][nq * 2 + 0], a[mi], b0, b1);
                mma16816(c[mi][nq * 2 + 1], a[mi], b2, b3);
            }
        }
    }

    __syncthreads();
    __half* Cs = sm;                      // [128][CST]
    #pragma unroll
    for (int mi = 0; mi < 2; mi++) {
        #pragma unroll
        for (int ni = 0; ni < 8; ni++) {
            int r0 = wm * 32 + mi * 16 + (lane >> 2);
            int col = wn * 64 + ni * 8 + 2 * (lane & 3);
            *(__half2*)(Cs + r0 * CST + col) =
                __floats2half2_rn(c[mi][ni][0], c[mi][ni][1]);
            *(__half2*)(Cs + (r0 + 8) * CST + col) =
                __floats2half2_rn(c[mi][ni][2], c[mi][ni][3]);
        }
    }
    __syncthreads();
    #pragma unroll
    for (int p = 0; p < 4; p++) {
        int row = p * 32 + (tid >> 3);
        int gr = m0 + row;
        if (gr < NN) {
            int col = (tid & 7) * 16;
            uint4 v0 = *(const uint4*)(Cs + row * CST + col);
            uint4 v1 = *(const uint4*)(Cs + row * CST + col + 8);
            __half* dst = g_y + (size_t)gr * ystride + n0 + col;
            *(uint4*)(dst) = v0;
            *(uint4*)(dst + 8) = v1;
        }
    }
}

// ---------------- gather for 64-wide layers (half2, dual accumulators) ------
template <bool RES, bool WF32>
__global__ void gather64_kernel(const float* __restrict__ resid,
                                float* __restrict__ outF) {
    int warpId = (blockIdx.x * blockDim.x + threadIdx.x) >> 5;
    int lane = threadIdx.x & 31;
    if (warpId >= NN) return;
    int i = warpId;
    int e0 = g_rowp[i], e1 = g_rowp[i + 1];
    float2 accA = make_float2(0.f, 0.f);
    float2 accB = make_float2(0.f, 0.f);
    int e = e0;
    for (; e + 1 < e1; e += 2) {
        int jk0 = __ldg(g_sjk + e);
        int jk1 = __ldg(g_sjk + e + 1);
        float4 w0 = __ldg(&g_sw[e]);
        float4 w1 = __ldg(&g_sw[e + 1]);
        {
            int j = jk0 & 0xFFFFF, kb = jk0 >> 20;
            const __half2* r = (const __half2*)(g_y + (size_t)j * YS1 + kb * 64 + 2 * lane);
            float2 f0 = __half22float2(__ldg(r));
            float2 f1 = __half22float2(__ldg(r + 32));
            float2 f2 = __half22float2(__ldg(r + 256));
            float2 f3 = __half22float2(__ldg(r + 288));
            accA.x += w0.x * f0.x + w0.y * f1.x + w0.z * f2.x + w0.w * f3.x;
            accA.y += w0.x * f0.y + w0.y * f1.y + w0.z * f2.y + w0.w * f3.y;
        }
        {
            int j = jk1 & 0xFFFFF, kb = jk1 >> 20;
            const __half2* r = (const __half2*)(g_y + (size_t)j * YS1 + kb * 64 + 2 * lane);
            float2 f0 = __half22float2(__ldg(r));
            float2 f1 = __half22float2(__ldg(r + 32));
            float2 f2 = __half22float2(__ldg(r + 256));
            float2 f3 = __half22float2(__ldg(r + 288));
            accB.x += w1.x * f0.x + w1.y * f1.x + w1.z * f2.x + w1.w * f3.x;
            accB.y += w1.x * f0.y + w1.y * f1.y + w1.z * f2.y + w1.w * f3.y;
        }
    }
    if (e < e1) {
        int jk0 = __ldg(g_sjk + e);
        float4 w0 = __ldg(&g_sw[e]);
        int j = jk0 & 0xFFFFF, kb = jk0 >> 20;
        const __half2* r = (const __half2*)(g_y + (size_t)j * YS1 + kb * 64 + 2 * lane);
        float2 f0 = __half22float2(__ldg(r));
        float2 f1 = __half22float2(__ldg(r + 32));
        float2 f2 = __half22float2(__ldg(r + 256));
        float2 f3 = __half22float2(__ldg(r + 288));
        accA.x += w0.x * f0.x + w0.y * f1.x + w0.z * f2.x + w0.w * f3.x;
        accA.y += w0.x * f0.y + w0.y * f1.y + w0.z * f2.y + w0.w * f3.y;
    }
    float2 acc = make_float2(accA.x + accB.x, accA.y + accB.y);
    float2 s = __half22float2(*(const __half2*)(g_y + (size_t)i * YS1 + 4096 + 2 * lane));
    float2 bv = *(const float2*)(g_bias + 2 * lane);
    float2 o = make_float2(acc.x + s.x + bv.x, acc.y + s.y + bv.y);
    if (RES) {
        float2 rv = *(const float2*)(resid + (size_t)i * 64 + 2 * lane);
        o.x += rv.x; o.y += rv.y;
    }
    if (WF32)
        *(float2*)(outF + (size_t)i * 64 + 2 * lane) = o;
    *(__half2*)(g_ah + (size_t)i * 64 + 2 * lane) =
        __floats2half2_rn(fmaxf(o.x, 0.f), fmaxf(o.y, 0.f));
}

// ---------------- final gather (Cout = 2) + /128 ----------------------------
__global__ void gatherF_kernel(const float* __restrict__ cb3,
                               const float* __restrict__ fb3,
                               float* __restrict__ out) {
    int warpId = (blockIdx.x * blockDim.x + threadIdx.x) >> 5;
    int lane = threadIdx.x & 31;
    if (warpId >= NN) return;
    int i = warpId;
    int e0 = g_rowp[i], e1 = g_rowp[i + 1];
    float accx = 0.f, accy = 0.f;
    for (int e = e0 + lane; e < e1; e += 32) {
        int jk = __ldg(g_sjk + e);
        float4 w = __ldg(&g_sw[e]);
        int j = jk & 0xFFFFF;
        int kb = jk >> 20;
        const __half2* r = (const __half2*)(g_y + (size_t)j * YS3 + kb * 2);
        float2 f0 = __half22float2(__ldg(r));
        float2 f1 = __half22float2(__ldg(r + 1));
        float2 f2 = __half22float2(__ldg(r + 8));
        float2 f3 = __half22float2(__ldg(r + 9));
        accx += w.x * f0.x + w.y * f1.x + w.z * f2.x + w.w * f3.x;
        accy += w.x * f0.y + w.y * f1.y + w.z * f2.y + w.w * f3.y;
    }
    #pragma unroll
    for (int off = 16; off > 0; off >>= 1) {
        accx += __shfl_down_sync(0xFFFFFFFFu, accx, off);
        accy += __shfl_down_sync(0xFFFFFFFFu, accy, off);
    }
    if (lane == 0) {
        float2 ds = __half22float2(*(const __half2*)(g_y + (size_t)i * YS3 + 128));
        out[2 * i]     = (accx + ds.x + cb3[0] + fb3[0]) * (1.f / 128.f);
        out[2 * i + 1] = (accy + ds.y + cb3[1] + fb3[1]) * (1.f / 128.f);
    }
}

// ---------------- launch ----------------------------------------------------
extern "C" void kernel_launch(void* const* d_in, const int* in_sizes, int n_in,
                              void* d_out, int out_size) {
    const float* pos  = (const float*)d_in[0];
    const float* feat = (const float*)d_in[1];
    const int*   ei   = (const int*)d_in[2];
    const int*   ej   = (const int*)d_in[3];
    const float* cw0 = (const float*)d_in[4];
    const float* cb0 = (const float*)d_in[5];
    const float* fw0 = (const float*)d_in[6];
    const float* fb0 = (const float*)d_in[7];
    const float* cw1 = (const float*)d_in[8];
    const float* cb1 = (const float*)d_in[9];
    const float* fw1 = (const float*)d_in[10];
    const float* fb1 = (const float*)d_in[11];
    const float* cw2 = (const float*)d_in[12];
    const float* cb2 = (const float*)d_in[13];
    const float* fw2 = (const float*)d_in[14];
    const float* fb2 = (const float*)d_in[15];
    const float* cw3 = (const float*)d_in[16];
    const float* cb3 = (const float*)d_in[17];
    const float* fw3 = (const float*)d_in[18];
    const float* fb3 = (const float*)d_in[19];
    float* out = (float*)d_out;
    int E = in_sizes[2];

    cudaFuncSetAttribute(gemm64_kernel,
                         cudaFuncAttributeMaxDynamicSharedMemorySize, SMEMB);
    const int SMEMA = (128 * GAST + 320 * GAST) * 2;   // 64512 B
    cudaFuncSetAttribute(gemmA_kernel,
                         cudaFuncAttributeMaxDynamicSharedMemorySize, SMEMA);

    float* aF; cudaGetSymbolAddress((void**)&aF, g_ansF);

    // edge counting sort (single atomic pass: rank captured in hist)
    zero_cnt_kernel<<<(NN + 256) / 256, 256>>>();
    hist_kernel<<<(E + 255) / 256, 256>>>(ei, E);
    scan1_kernel<<<SCAN_B, 1024>>>();
    scan2_kernel<<<1, 64>>>();
    scan3_kernel<<<SCAN_B, 1024>>>();
    scatter_kernel<<<(E + 255) / 256, 256>>>(pos, ei, ej, E);

    // layer 0 (moment formulation)
    pack0_kernel<<<(320 * 64 + 255) / 256, 256>>>(cw0, fw0, cb0, fb0);
    mom0_kernel<<<NN / 8, 256>>>(feat);
    gemmA_kernel<<<391, 256, SMEMA>>>();

    // layer 1
    pack_kernel<<<(64 * NPAD + 255) / 256, 256>>>(cw1, fw1, cb1, fb1, 4160, NPAD, 6, 63, 64);
    gemm64_kernel<<<dim3(33, 391), 256, SMEMB>>>(YS1);
    gather64_kernel<false, true><<<(NN * 32 + 255) / 256, 256>>>(nullptr, aF);

    // layer 2 (residual = ansF)
    pack_kernel<<<(64 * NPAD + 255) / 256, 256>>>(cw2, fw2, cb2, fb2, 4160, NPAD, 6, 63, 64);
    gemm64_kernel<<<dim3(33, 391), 256, SMEMB>>>(YS1);
    gather64_kernel<true, false><<<(NN * 32 + 255) / 256, 256>>>(aF, nullptr);

    // layer 3
    pack_kernel<<<(64 * 256 + 255) / 256, 256>>>(cw3, fw3, cb3, fb3, 130, 256, 1, 1, 0);
    gemm64_kernel<<<dim3(2, 391), 256, SMEMB>>>(YS3);
    gatherF_kernel<<<(NN * 32 + 255) / 256, 256>>>(cb3, fb3, out);
}

// round 11
// speedup vs baseline: 2.1341x; 1.0261x over previous
#include <cuda_runtime.h>
#include <cuda_fp16.h>
#include <stdint.h>

#define NN 50000
#define EE 1600000
#define YS1 4224          // padded y stride (halves) for 64->64 layers (33*128)
#define YS3 256           // y stride for layer3
#define NPAD 4224         // packed-weight column pad (layers 1/2)
#define SCAN_B 49         // ceil(50000/1024)

// ---------------- device scratch (no runtime allocation allowed) ------------
__device__ __align__(16) __half g_y[(size_t)NN * YS1];   // 422 MB
__device__ __align__(16) __half g_wc1[64 * NPAD];
__device__ __align__(16) __half g_wc2[64 * NPAD];
__device__ __align__(16) __half g_wc3[64 * 256];
__device__ __align__(16) __half g_ah[NN * 64];           // relu(ans) fp16 (GEMM A)
__device__ __align__(16) float  g_ansF[NN * 64];         // layer1 out fp32 (residual)
__device__ __align__(16) __half g_m0[(size_t)NN * 320];  // layer0 moments + x, fp16
__device__ __align__(16) __half g_wb0[320 * 64];         // layer0 packed weights
__device__ float  g_bias0[64];
__device__ float  g_bias1[64];
__device__ float  g_bias2[64];
__device__ int    g_cnt[NN + 1];
__device__ int    g_rowp[NN + 1];
__device__ int    g_rank[EE];
__device__ int    g_bsum[SCAN_B];
__device__ int    g_boff[SCAN_B + 1];
__device__ int    g_sjk[EE];                 // j | (kb<<20)
__device__ __align__(16) float4 g_sw[EE];    // 4 hat-product weights

// ---------------- mma / async helpers ----------------------------------------
__device__ __forceinline__ void ldsm4(uint32_t& r0, uint32_t& r1, uint32_t& r2,
                                      uint32_t& r3, uint32_t addr) {
    asm volatile("ldmatrix.sync.aligned.m8n8.x4.shared.b16 {%0,%1,%2,%3}, [%4];"
                 : "=r"(r0), "=r"(r1), "=r"(r2), "=r"(r3) : "r"(addr));
}
__device__ __forceinline__ void ldsm4t(uint32_t& r0, uint32_t& r1, uint32_t& r2,
                                       uint32_t& r3, uint32_t addr) {
    asm volatile("ldmatrix.sync.aligned.m8n8.x4.trans.shared.b16 {%0,%1,%2,%3}, [%4];"
                 : "=r"(r0), "=r"(r1), "=r"(r2), "=r"(r3) : "r"(addr));
}
__device__ __forceinline__ void mma16816(float* c, const uint32_t* a,
                                         uint32_t b0, uint32_t b1) {
    asm volatile(
        "mma.sync.aligned.m16n8k16.row.col.f32.f16.f16.f32 "
        "{%0,%1,%2,%3}, {%4,%5,%6,%7}, {%8,%9}, {%0,%1,%2,%3};"
        : "+f"(c[0]), "+f"(c[1]), "+f"(c[2]), "+f"(c[3])
        : "r"(a[0]), "r"(a[1]), "r"(a[2]), "r"(a[3]), "r"(b0), "r"(b1));
}
__device__ __forceinline__ void cpa16(uint32_t dst, const void* src) {
    asm volatile("cp.async.cg.shared.global [%0], [%1], 16;" :: "r"(dst), "l"(src));
}
#define CP_COMMIT() asm volatile("cp.async.commit_group;")
#define CP_WAIT1()  asm volatile("cp.async.wait_group 1;")
#define CP_WAIT0()  asm volatile("cp.async.wait_group 0;")

// ---------------- combined weight pack + cnt zero ----------------------------
#define R0 (320 * 64)
#define R1 (64 * NPAD)
#define R3 (64 * 256)
#define PACK_TOT (R0 + 2 * R1 + R3 + NN + 1)

__device__ __forceinline__ float wcat_val(const float* CW, const float* FW,
                                          int k, int col, int ncols,
                                          int coutShift, int coutMask) {
    if (col >= ncols) return 0.f;
    int cout = 1 << coutShift;
    int kcoutTot = 64 << coutShift;
    if (col < kcoutTot) {
        int kk = col >> coutShift;
        int co = col & coutMask;
        return __ldg(CW + (size_t)(kk * 64 + k) * cout + co);
    }
    return __ldg(FW + (size_t)k * cout + (col - kcoutTot));
}

__global__ void packAll_kernel(
    const float* __restrict__ cw0, const float* __restrict__ fw0,
    const float* __restrict__ cb0, const float* __restrict__ fb0,
    const float* __restrict__ cw1, const float* __restrict__ fw1,
    const float* __restrict__ cb1, const float* __restrict__ fb1,
    const float* __restrict__ cw2, const float* __restrict__ fw2,
    const float* __restrict__ cb2, const float* __restrict__ fb2,
    const float* __restrict__ cw3, const float* __restrict__ fw3) {
    int idx = blockIdx.x * blockDim.x + threadIdx.x;
    if (idx >= PACK_TOT) return;
    if (idx < R0) {
        int row = idx >> 6, co = idx & 63;
        float v = 0.f;
        if (row < 256) {
            int kb = row >> 2, c = row & 3;
            if (co >= 32) v = __ldg(cw0 + (size_t)(kb * 4 + c) * 32 + (co - 32));
        } else if (row < 260) {
            int c = row - 256;
            if (co < 32) v = __ldg(fw0 + (size_t)c * 32 + co);
        }
        g_wb0[idx] = __float2half(v);
        if (idx < 64)
            g_bias0[idx] = (idx < 32) ? __ldg(fb0 + idx) : __ldg(cb0 + idx - 32);
        return;
    }
    idx -= R0;
    if (idx < R1) {
        int k = idx / NPAD, col = idx - k * NPAD;
        g_wc1[idx] = __float2half(wcat_val(cw1, fw1, k, col, 4160, 6, 63));
        if (idx < 64) g_bias1[idx] = __ldg(cb1 + idx) + __ldg(fb1 + idx);
        return;
    }
    idx -= R1;
    if (idx < R1) {
        int k = idx / NPAD, col = idx - k * NPAD;
        g_wc2[idx] = __float2half(wcat_val(cw2, fw2, k, col, 4160, 6, 63));
        if (idx < 64) g_bias2[idx] = __ldg(cb2 + idx) + __ldg(fb2 + idx);
        return;
    }
    idx -= R1;
    if (idx < R3) {
        int k = idx >> 8, col = idx & 255;
        g_wc3[idx] = __float2half(wcat_val(cw3, fw3, k, col, 130, 1, 1));
        return;
    }
    idx -= R3;
    g_cnt[idx] = 0;
}

// ---------------- edge preprocessing ----------------------------------------
__global__ void hist_kernel(const int* __restrict__ ei, int E) {
    int e = blockIdx.x * blockDim.x + threadIdx.x;
    if (e < E) g_rank[e] = atomicAdd(&g_cnt[__ldg(ei + e)], 1);
}

__global__ void scan1_kernel() {
    __shared__ int sh[1024];
    int b = blockIdx.x, tid = threadIdx.x;
    int idx = b * 1024 + tid;
    int v = (idx < NN) ? g_cnt[idx] : 0;
    sh[tid] = v;
    __syncthreads();
    for (int off = 512; off > 0; off >>= 1) {
        if (tid < off) sh[tid] += sh[tid + off];
        __syncthreads();
    }
    if (tid == 0) g_bsum[b] = sh[0];
}

__global__ void scan2_kernel() {
    __shared__ int sh[64];
    int tid = threadIdx.x;
    int v = (tid < SCAN_B) ? g_bsum[tid] : 0;
    sh[tid] = v;
    __syncthreads();
    for (int off = 1; off < 64; off <<= 1) {
        int t = (tid >= off) ? sh[tid - off] : 0;
        __syncthreads();
        sh[tid] += t;
        __syncthreads();
    }
    if (tid < SCAN_B) g_boff[tid] = sh[tid] - v;
    if (tid == SCAN_B - 1) g_boff[SCAN_B] = sh[tid];
}

__global__ void scan3_kernel() {
    __shared__ int sh[1024];
    int b = blockIdx.x, tid = threadIdx.x;
    int idx = b * 1024 + tid;
    int v = (idx < NN) ? g_cnt[idx] : 0;
    int orig = v;
    sh[tid] = v;
    __syncthreads();
    for (int off = 1; off < 1024; off <<= 1) {
        int t = (tid >= off) ? sh[tid - off] : 0;
        __syncthreads();
        sh[tid] += t;
        __syncthreads();
    }
    if (idx < NN)
        g_rowp[idx] = g_boff[b] + sh[tid] - orig;
    if (b == 0 && tid == 0) g_rowp[NN] = g_boff[SCAN_B];
}

__global__ void scatter_kernel(const float* __restrict__ pos,
                               const int* __restrict__ ei,
                               const int* __restrict__ ej, int E) {
    int e = blockIdx.x * blockDim.x + threadIdx.x;
    if (e >= E) return;
    int i = __ldg(ei + e), j = __ldg(ej + e);
    const float2* p2 = (const float2*)pos;
    float2 pi = __ldg(p2 + i);
    float2 pj = __ldg(p2 + j);
    float dx = pi.x - pj.x;
    float dy = pi.y - pj.y;
    dx = fminf(1.f, fmaxf(-1.f, dx));
    dy = fminf(1.f, fmaxf(-1.f, dy));
    float m = (i != j) ? 1.f : 0.f;
    float r = sqrtf(dx * dx + dy * dy + 1e-12f);
    float u = fminf(1.f, fmaxf(-1.f, 2.f * r - 1.f));
    float v = atan2f(dy, dx) * 0.318309886183790672f;   // 1/pi
    float su = (u + 1.f) * 3.5f;
    int   iu = min(6, (int)floorf(su));
    float tu = su - (float)iu;
    float sv = (v + 1.f) * 3.5f;
    int   iv = min(6, (int)floorf(sv));
    float tv = sv - (float)iv;
    float4 w = make_float4((1.f - tu) * (1.f - tv) * m,
                           (1.f - tu) * tv * m,
                           tu * (1.f - tv) * m,
                           tu * tv * m);
    int kb = iu * 8 + iv;
    int p = g_rowp[i] + g_rank[e];
    g_sjk[p] = j | (kb << 20);
    g_sw[p] = w;
}

// ---------------- layer 0: moment accumulation (Cin=4) ----------------------
__global__ void mom0_kernel(const float* __restrict__ X) {
    __shared__ float M0s[8 * 256];
    int warp = threadIdx.x >> 5, lane = threadIdx.x & 31;
    int node = blockIdx.x * 8 + warp;
    float* M = M0s + warp * 256;
    #pragma unroll
    for (int r = 0; r < 8; r++) M[r * 32 + lane] = 0.f;
    __syncwarp();
    if (node < NN) {
        int e0 = g_rowp[node], e1 = g_rowp[node + 1];
        int t = lane >> 2, c = lane & 3;
        bool act = lane < 16;
        int kadd = (t & 1) + ((t >> 1) << 3);
        for (int e = e0; e < e1; e++) {
            int jk = __ldg(g_sjk + e);
            float4 w = __ldg(&g_sw[e]);
            int j = jk & 0xFFFFF;
            int kb = jk >> 20;
            float4 xv = __ldg((const float4*)X + j);
            if (act) {
                float wt = (t == 0) ? w.x : (t == 1) ? w.y : (t == 2) ? w.z : w.w;
                float xc = (c == 0) ? xv.x : (c == 1) ? xv.y : (c == 2) ? xv.z : xv.w;
                M[(kb + kadd) * 4 + c] += wt * xc;
            }
        }
        __syncwarp();
        __half* dst = g_m0 + (size_t)node * 320;
        #pragma unroll
        for (int r = 0; r < 4; r++) {
            int idx = r * 64 + 2 * lane;
            *(__half2*)(dst + idx) = __floats2half2_rn(M[idx], M[idx + 1]);
        }
        float4 xi = __ldg((const float4*)X + node);
        __half2 hv;
        if (lane == 0)      hv = __floats2half2_rn(xi.x, xi.y);
        else if (lane == 1) hv = __floats2half2_rn(xi.z, xi.w);
        else                hv = __floats2half2_rn(0.f, 0.f);
        *(__half2*)(dst + 256 + 2 * lane) = hv;
    }
}

// ---------------- layer 0 GEMM: ans0 = [M0|x] @ Wb0, bias, relu -> g_ah -----
#define GAST 72
__global__ void __launch_bounds__(256)
gemmA_kernel() {
    extern __shared__ __half smA[];
    __half* As = smA;                    // [128][GAST]
    __half* Bs = smA + 128 * GAST;       // [320][GAST]
    int m0 = blockIdx.x * 128;
    int tid = threadIdx.x;

    #pragma unroll
    for (int it = 0; it < 10; it++) {
        int idx = tid + it * 256;
        int row = idx >> 3;
        int c8 = idx & 7;
        uint4 v = __ldg((const uint4*)(g_wb0 + row * 64 + c8 * 8));
        *(uint4*)(Bs + row * GAST + c8 * 8) = v;
    }

    int warp = tid >> 5, lane = tid & 31;
    int wm = warp & 3, wn = warp >> 2;
    uint32_t asB = (uint32_t)__cvta_generic_to_shared(As);
    uint32_t bsB = (uint32_t)__cvta_generic_to_shared(Bs);

    float c[2][4][4];
    #pragma unroll
    for (int mi = 0; mi < 2; mi++)
        #pragma unroll
        for (int ni = 0; ni < 4; ni++)
            #pragma unroll
            for (int p = 0; p < 4; p++) c[mi][ni][p] = 0.f;

    for (int kc = 0; kc < 5; kc++) {
        __syncthreads();
        #pragma unroll
        for (int it = 0; it < 4; it++) {
            int idx = tid + it * 256;
            int row = idx >> 3;
            int c8 = idx & 7;
            uint4 v = make_uint4(0, 0, 0, 0);
            if (m0 + row < NN)
                v = __ldg((const uint4*)(g_m0 + (size_t)(m0 + row) * 320 + kc * 64 + c8 * 8));
            *(uint4*)(As + row * GAST + c8 * 8) = v;
        }
        __syncthreads();
        #pragma unroll
        for (int ks = 0; ks < 4; ks++) {
            int k0 = ks * 16;
            uint32_t a[2][4];
            #pragma unroll
            for (int mi = 0; mi < 2; mi++) {
                int row = wm * 32 + mi * 16 + (lane & 15);
                int col = k0 + ((lane >> 4) << 3);
                ldsm4(a[mi][0], a[mi][1], a[mi][2], a[mi][3],
                      asB + (row * GAST + col) * 2);
            }
            int brow = kc * 64 + k0 + (lane & 15);
            #pragma unroll
            for (int nq = 0; nq < 2; nq++) {
                int bcol = wn * 32 + nq * 16 + ((lane >> 4) << 3);
                uint32_t b0, b1, b2, b3;
                ldsm4t(b0, b1, b2, b3, bsB + (brow * GAST + bcol) * 2);
                #pragma unroll
                for (int mi = 0; mi < 2; mi++) {
                    mma16816(c[mi][nq * 2 + 0], a[mi], b0, b1);
                    mma16816(c[mi][nq * 2 + 1], a[mi], b2, b3);
                }
            }
        }
    }

    #pragma unroll
    for (int mi = 0; mi < 2; mi++) {
        #pragma unroll
        for (int ni = 0; ni < 4; ni++) {
            int row0 = m0 + wm * 32 + mi * 16 + (lane >> 2);
            int col = wn * 32 + ni * 8 + 2 * (lane & 3);
            float2 bv = *(const float2*)(g_bias0 + col);
            if (row0 < NN)
                *(__half2*)(g_ah + (size_t)row0 * 64 + col) = __floats2half2_rn(
                    fmaxf(c[mi][ni][0] + bv.x, 0.f), fmaxf(c[mi][ni][1] + bv.y, 0.f));
            int row1 = row0 + 8;
            if (row1 < NN)
                *(__half2*)(g_ah + (size_t)row1 * 64 + col) = __floats2half2_rn(
                    fmaxf(c[mi][ni][2] + bv.x, 0.f), fmaxf(c[mi][ni][3] + bv.y, 0.f));
        }
    }
}

// ---------------- persistent-A main GEMM: Y = Ah @ Wcat ---------------------
// block = (m-tile 128 rows) x (n-split); stages A once, loops n-tiles with
// cp.async double-buffered B; per-tile epilogue via smem -> 256B-row stores.
#define AST 72
#define BST 136
#define CST 136
#define PSMEM ((128 * AST + 2 * 64 * BST + 128 * CST) * 2)   // 88064 B

__global__ void __launch_bounds__(256, 2)
gemmP_kernel(const __half* __restrict__ wc, int wstride,
             int tilesPerSplit, int ntilesTot, int ystride) {
    extern __shared__ __half sp[];
    __half* As = sp;                                   // [128][AST]
    __half* Bs0 = sp + 128 * AST;                      // [64][BST] x2
    __half* Cs = sp + 128 * AST + 2 * 64 * BST;        // [128][CST]
    int m0 = blockIdx.x * 128;
    int t0 = blockIdx.y * tilesPerSplit;
    int t1 = min(ntilesTot, t0 + tilesPerSplit);
    int tid = threadIdx.x;
    int warp = tid >> 5, lane = tid & 31;
    int wm = warp & 3, wn = warp >> 2;

    // stage A once
    #pragma unroll
    for (int it = 0; it < 4; it++) {
        int idx = tid + it * 256;
        int row = idx >> 3;
        int c8 = idx & 7;
        uint4 v = make_uint4(0, 0, 0, 0);
        if (m0 + row < NN)
            v = __ldg((const uint4*)(g_ah + (size_t)(m0 + row) * 64 + c8 * 8));
        *(uint4*)(As + row * AST + c8 * 8) = v;
    }

    auto loadB = [&](int buf, int t) {
        uint32_t bb = (uint32_t)__cvta_generic_to_shared(Bs0 + buf * 64 * BST);
        int n0 = t * 128;
        #pragma unroll
        for (int it = 0; it < 4; it++) {
            int idx = tid + it * 256;      // 1024 x 16B
            int row = idx >> 4;
            int c8 = idx & 15;
            cpa16(bb + (row * BST + c8 * 8) * 2,
                  wc + (size_t)row * wstride + n0 + c8 * 8);
        }
        CP_COMMIT();
    };

    uint32_t asBase = (uint32_t)__cvta_generic_to_shared(As);
    loadB(0, t0);

    for (int t = t0; t < t1; t++) {
        int buf = (t - t0) & 1;
        if (t + 1 < t1) loadB(buf ^ 1, t + 1);
        if (t + 1 < t1) { CP_WAIT1(); } else { CP_WAIT0(); }
        __syncthreads();

        uint32_t bsBase = (uint32_t)__cvta_generic_to_shared(Bs0 + buf * 64 * BST);
        float c[2][8][4];
        #pragma unroll
        for (int mi = 0; mi < 2; mi++)
            #pragma unroll
            for (int ni = 0; ni < 8; ni++)
                #pragma unroll
                for (int p = 0; p < 4; p++) c[mi][ni][p] = 0.f;

        #pragma unroll
        for (int ks = 0; ks < 4; ks++) {
            int k0 = ks * 16;
            uint32_t a[2][4];
            #pragma unroll
            for (int mi = 0; mi < 2; mi++) {
                int row = wm * 32 + mi * 16 + (lane & 15);
                int col = k0 + ((lane >> 4) << 3);
                ldsm4(a[mi][0], a[mi][1], a[mi][2], a[mi][3],
                      asBase + (row * AST + col) * 2);
            }
            #pragma unroll
            for (int nq = 0; nq < 4; nq++) {
                int row = k0 + (lane & 15);
                int col = wn * 64 + nq * 16 + ((lane >> 4) << 3);
                uint32_t b0, b1, b2, b3;
                ldsm4t(b0, b1, b2, b3, bsBase + (row * BST + col) * 2);
                #pragma unroll
                for (int mi = 0; mi < 2; mi++) {
                    mma16816(c[mi][nq * 2 + 0], a[mi], b0, b1);
                    mma16816(c[mi][nq * 2 + 1], a[mi], b2, b3);
                }
            }
        }

        // epilogue: fragments -> Cs -> coalesced 256B-row stores
        __syncthreads();
        #pragma unroll
        for (int mi = 0; mi < 2; mi++) {
            #pragma unroll
            for (int ni = 0; ni < 8; ni++) {
                int r0 = wm * 32 + mi * 16 + (lane >> 2);
                int col = wn * 64 + ni * 8 + 2 * (lane & 3);
                *(__half2*)(Cs + r0 * CST + col) =
                    __floats2half2_rn(c[mi][ni][0], c[mi][ni][1]);
                *(__half2*)(Cs + (r0 + 8) * CST + col) =
                    __floats2half2_rn(c[mi][ni][2], c[mi][ni][3]);
            }
        }
        __syncthreads();
        int n0 = t * 128;
        #pragma unroll
        for (int p = 0; p < 4; p++) {
            int row = p * 32 + (tid >> 3);
            int gr = m0 + row;
            if (gr < NN) {
                int col = (tid & 7) * 16;
                uint4 v0 = *(const uint4*)(Cs + row * CST + col);
                uint4 v1 = *(const uint4*)(Cs + row * CST + col + 8);
                __half* dst = g_y + (size_t)gr * ystride + n0 + col;
                *(uint4*)(dst) = v0;
                *(uint4*)(dst + 8) = v1;
            }
        }
        __syncthreads();
    }
}

// ---------------- gather for 64-wide layers (half2, dual accumulators) ------
template <bool RES, bool WF32>
__global__ void gather64_kernel(const float* __restrict__ bias,
                                const float* __restrict__ resid,
                                float* __restrict__ outF) {
    int warpId = (blockIdx.x * blockDim.x + threadIdx.x) >> 5;
    int lane = threadIdx.x & 31;
    if (warpId >= NN) return;
    int i = warpId;
    int e0 = g_rowp[i], e1 = g_rowp[i + 1];
    float2 accA = make_float2(0.f, 0.f);
    float2 accB = make_float2(0.f, 0.f);
    int e = e0;
    for (; e + 1 < e1; e += 2) {
        int jk0 = __ldg(g_sjk + e);
        int jk1 = __ldg(g_sjk + e + 1);
        float4 w0 = __ldg(&g_sw[e]);
        float4 w1 = __ldg(&g_sw[e + 1]);
        {
            int j = jk0 & 0xFFFFF, kb = jk0 >> 20;
            const __half2* r = (const __half2*)(g_y + (size_t)j * YS1 + kb * 64 + 2 * lane);
            float2 f0 = __half22float2(__ldg(r));
            float2 f1 = __half22float2(__ldg(r + 32));
            float2 f2 = __half22float2(__ldg(r + 256));
            float2 f3 = __half22float2(__ldg(r + 288));
            accA.x += w0.x * f0.x + w0.y * f1.x + w0.z * f2.x + w0.w * f3.x;
            accA.y += w0.x * f0.y + w0.y * f1.y + w0.z * f2.y + w0.w * f3.y;
        }
        {
            int j = jk1 & 0xFFFFF, kb = jk1 >> 20;
            const __half2* r = (const __half2*)(g_y + (size_t)j * YS1 + kb * 64 + 2 * lane);
            float2 f0 = __half22float2(__ldg(r));
            float2 f1 = __half22float2(__ldg(r + 32));
            float2 f2 = __half22float2(__ldg(r + 256));
            float2 f3 = __half22float2(__ldg(r + 288));
            accB.x += w1.x * f0.x + w1.y * f1.x + w1.z * f2.x + w1.w * f3.x;
            accB.y += w1.x * f0.y + w1.y * f1.y + w1.z * f2.y + w1.w * f3.y;
        }
    }
    if (e < e1) {
        int jk0 = __ldg(g_sjk + e);
        float4 w0 = __ldg(&g_sw[e]);
        int j = jk0 & 0xFFFFF, kb = jk0 >> 20;
        const __half2* r = (const __half2*)(g_y + (size_t)j * YS1 + kb * 64 + 2 * lane);
        float2 f0 = __half22float2(__ldg(r));
        float2 f1 = __half22float2(__ldg(r + 32));
        float2 f2 = __half22float2(__ldg(r + 256));
        float2 f3 = __half22float2(__ldg(r + 288));
        accA.x += w0.x * f0.x + w0.y * f1.x + w0.z * f2.x + w0.w * f3.x;
        accA.y += w0.x * f0.y + w0.y * f1.y + w0.z * f2.y + w0.w * f3.y;
    }
    float2 acc = make_float2(accA.x + accB.x, accA.y + accB.y);
    float2 s = __half22float2(*(const __half2*)(g_y + (size_t)i * YS1 + 4096 + 2 * lane));
    float2 bv = *(const float2*)(bias + 2 * lane);
    float2 o = make_float2(acc.x + s.x + bv.x, acc.y + s.y + bv.y);
    if (RES) {
        float2 rv = *(const float2*)(resid + (size_t)i * 64 + 2 * lane);
        o.x += rv.x; o.y += rv.y;
    }
    if (WF32)
        *(float2*)(outF + (size_t)i * 64 + 2 * lane) = o;
    *(__half2*)(g_ah + (size_t)i * 64 + 2 * lane) =
        __floats2half2_rn(fmaxf(o.x, 0.f), fmaxf(o.y, 0.f));
}

// ---------------- final gather (Cout = 2) + /128 ----------------------------
__global__ void gatherF_kernel(const float* __restrict__ cb3,
                               const float* __restrict__ fb3,
                               float* __restrict__ out) {
    int warpId = (blockIdx.x * blockDim.x + threadIdx.x) >> 5;
    int lane = threadIdx.x & 31;
    if (warpId >= NN) return;
    int i = warpId;
    int e0 = g_rowp[i], e1 = g_rowp[i + 1];
    float accx = 0.f, accy = 0.f;
    for (int e = e0 + lane; e < e1; e += 32) {
        int jk = __ldg(g_sjk + e);
        float4 w = __ldg(&g_sw[e]);
        int j = jk & 0xFFFFF;
        int kb = jk >> 20;
        const __half2* r = (const __half2*)(g_y + (size_t)j * YS3 + kb * 2);
        float2 f0 = __half22float2(__ldg(r));
        float2 f1 = __half22float2(__ldg(r + 1));
        float2 f2 = __half22float2(__ldg(r + 8));
        float2 f3 = __half22float2(__ldg(r + 9));
        accx += w.x * f0.x + w.y * f1.x + w.z * f2.x + w.w * f3.x;
        accy += w.x * f0.y + w.y * f1.y + w.z * f2.y + w.w * f3.y;
    }
    #pragma unroll
    for (int off = 16; off > 0; off >>= 1) {
        accx += __shfl_down_sync(0xFFFFFFFFu, accx, off);
        accy += __shfl_down_sync(0xFFFFFFFFu, accy, off);
    }
    if (lane == 0) {
        float2 ds = __half22float2(*(const __half2*)(g_y + (size_t)i * YS3 + 128));
        out[2 * i]     = (accx + ds.x + cb3[0] + fb3[0]) * (1.f / 128.f);
        out[2 * i + 1] = (accy + ds.y + cb3[1] + fb3[1]) * (1.f / 128.f);
    }
}

// ---------------- launch ----------------------------------------------------
extern "C" void kernel_launch(void* const* d_in, const int* in_sizes, int n_in,
                              void* d_out, int out_size) {
    const float* pos  = (const float*)d_in[0];
    const float* feat = (const float*)d_in[1];
    const int*   ei   = (const int*)d_in[2];
    const int*   ej   = (const int*)d_in[3];
    const float* cw0 = (const float*)d_in[4];
    const float* cb0 = (const float*)d_in[5];
    const float* fw0 = (const float*)d_in[6];
    const float* fb0 = (const float*)d_in[7];
    const float* cw1 = (const float*)d_in[8];
    const float* cb1 = (const float*)d_in[9];
    const float* fw1 = (const float*)d_in[10];
    const float* fb1 = (const float*)d_in[11];
    const float* cw2 = (const float*)d_in[12];
    const float* cb2 = (const float*)d_in[13];
    const float* fw2 = (const float*)d_in[14];
    const float* fb2 = (const float*)d_in[15];
    const float* cw3 = (const float*)d_in[16];
    const float* cb3 = (const float*)d_in[17];
    const float* fw3 = (const float*)d_in[18];
    const float* fb3 = (const float*)d_in[19];
    float* out = (float*)d_out;
    int E = in_sizes[2];

    const int SMEMA = (128 * GAST + 320 * GAST) * 2;   // 64512 B
    cudaFuncSetAttribute(gemmA_kernel,
                         cudaFuncAttributeMaxDynamicSharedMemorySize, SMEMA);
    cudaFuncSetAttribute(gemmP_kernel,
                         cudaFuncAttributeMaxDynamicSharedMemorySize, PSMEM);

    float* aF;  cudaGetSymbolAddress((void**)&aF, g_ansF);
    __half* w1; cudaGetSymbolAddress((void**)&w1, g_wc1);
    __half* w2; cudaGetSymbolAddress((void**)&w2, g_wc2);
    __half* w3; cudaGetSymbolAddress((void**)&w3, g_wc3);
    float* b1;  cudaGetSymbolAddress((void**)&b1, g_bias1);
    float* b2;  cudaGetSymbolAddress((void**)&b2, g_bias2);

    // all weight packing + cnt zero in one launch
    packAll_kernel<<<(PACK_TOT + 255) / 256, 256>>>(
        cw0, fw0, cb0, fb0, cw1, fw1, cb1, fb1,
        cw2, fw2, cb2, fb2, cw3, fw3);

    // edge counting sort (single atomic pass)
    hist_kernel<<<(E + 255) / 256, 256>>>(ei, E);
    scan1_kernel<<<SCAN_B, 1024>>>();
    scan2_kernel<<<1, 64>>>();
    scan3_kernel<<<SCAN_B, 1024>>>();
    scatter_kernel<<<(E + 255) / 256, 256>>>(pos, ei, ej, E);

    // layer 0 (moment formulation)
    mom0_kernel<<<NN / 8, 256>>>(feat);
    gemmA_kernel<<<391, 256, SMEMA>>>();

    // layer 1
    gemmP_kernel<<<dim3(391, 3), 256, PSMEM>>>(w1, NPAD, 11, 33, YS1);
    gather64_kernel<false, true><<<(NN * 32 + 255) / 256, 256>>>(b1, nullptr, aF);

    // layer 2 (residual = ansF)
    gemmP_kernel<<<dim3(391, 3), 256, PSMEM>>>(w2, NPAD, 11, 33, YS1);
    gather64_kernel<true, false><<<(NN * 32 + 255) / 256, 256>>>(b2, aF, nullptr);

    // layer 3
    gemmP_kernel<<<dim3(391, 1), 256, PSMEM>>>(w3, 256, 2, 2, YS3);
    gatherF_kernel<<<(NN * 32 + 255) / 256, 256>>>(cb3, fb3, out);
}

// round 12
// speedup vs baseline: 2.3221x; 1.0881x over previous
#include <cuda_runtime.h>
#include <cuda_fp16.h>
#include <stdint.h>

#define NN 50000
#define EE 1600000
#define YS1 4224          // padded y stride (halves) for 64->64 layers (33*128)
#define YS3 256           // y stride for layer3
#define NPAD 4224         // packed-weight column pad (layers 1/2)
#define SCAN_B 49         // ceil(50000/1024)

// ---------------- device scratch (no runtime allocation allowed) ------------
__device__ __align__(16) __half g_y[(size_t)NN * YS1];   // 422 MB
__device__ __align__(16) __half g_wc1[64 * NPAD];
__device__ __align__(16) __half g_wc2[64 * NPAD];
__device__ __align__(16) __half g_wc3[64 * 256];
__device__ __align__(16) __half g_ah[NN * 64];           // relu(ans) fp16 (GEMM A)
__device__ __align__(16) float  g_ansF[NN * 64];         // layer1 out fp32 (residual)
__device__ __align__(16) __half g_m0[(size_t)NN * 320];  // layer0 moments + x, fp16
__device__ __align__(16) __half g_wb0[320 * 64];         // layer0 packed weights
__device__ float  g_bias0[64];
__device__ float  g_bias1[64];
__device__ float  g_bias2[64];
__device__ int    g_cnt[NN + 1];
__device__ int    g_rowp[NN + 1];
__device__ int    g_rank[EE];
__device__ int    g_bsum[SCAN_B];
__device__ int    g_boff[SCAN_B + 1];
// edge record: .x = j | kb<<20 | m<<31 ; .y/.z/.w = w0,w1,w2 (fp32 bits)
__device__ __align__(16) uint4 g_ed[EE];

// ---------------- mma / async helpers ----------------------------------------
__device__ __forceinline__ void ldsm4(uint32_t& r0, uint32_t& r1, uint32_t& r2,
                                      uint32_t& r3, uint32_t addr) {
    asm volatile("ldmatrix.sync.aligned.m8n8.x4.shared.b16 {%0,%1,%2,%3}, [%4];"
                 : "=r"(r0), "=r"(r1), "=r"(r2), "=r"(r3) : "r"(addr));
}
__device__ __forceinline__ void ldsm4t(uint32_t& r0, uint32_t& r1, uint32_t& r2,
                                       uint32_t& r3, uint32_t addr) {
    asm volatile("ldmatrix.sync.aligned.m8n8.x4.trans.shared.b16 {%0,%1,%2,%3}, [%4];"
                 : "=r"(r0), "=r"(r1), "=r"(r2), "=r"(r3) : "r"(addr));
}
__device__ __forceinline__ void mma16816(float* c, const uint32_t* a,
                                         uint32_t b0, uint32_t b1) {
    asm volatile(
        "mma.sync.aligned.m16n8k16.row.col.f32.f16.f16.f32 "
        "{%0,%1,%2,%3}, {%4,%5,%6,%7}, {%8,%9}, {%0,%1,%2,%3};"
        : "+f"(c[0]), "+f"(c[1]), "+f"(c[2]), "+f"(c[3])
        : "r"(a[0]), "r"(a[1]), "r"(a[2]), "r"(a[3]), "r"(b0), "r"(b1));
}
__device__ __forceinline__ void cpa16(uint32_t dst, const void* src) {
    asm volatile("cp.async.cg.shared.global [%0], [%1], 16;" :: "r"(dst), "l"(src));
}
#define CP_COMMIT() asm volatile("cp.async.commit_group;")
#define CP_WAIT1()  asm volatile("cp.async.wait_group 1;")
#define CP_WAIT0()  asm volatile("cp.async.wait_group 0;")

// ---------------- combined weight pack + cnt zero ----------------------------
#define R0 (320 * 64)
#define R1 (64 * NPAD)
#define R3 (64 * 256)
#define PACK_TOT (R0 + 2 * R1 + R3 + NN + 1)

__device__ __forceinline__ float wcat_val(const float* CW, const float* FW,
                                          int k, int col, int ncols,
                                          int coutShift, int coutMask) {
    if (col >= ncols) return 0.f;
    int cout = 1 << coutShift;
    int kcoutTot = 64 << coutShift;
    if (col < kcoutTot) {
        int kk = col >> coutShift;
        int co = col & coutMask;
        return __ldg(CW + (size_t)(kk * 64 + k) * cout + co);
    }
    return __ldg(FW + (size_t)k * cout + (col - kcoutTot));
}

__global__ void packAll_kernel(
    const float* __restrict__ cw0, const float* __restrict__ fw0,
    const float* __restrict__ cb0, const float* __restrict__ fb0,
    const float* __restrict__ cw1, const float* __restrict__ fw1,
    const float* __restrict__ cb1, const float* __restrict__ fb1,
    const float* __restrict__ cw2, const float* __restrict__ fw2,
    const float* __restrict__ cb2, const float* __restrict__ fb2,
    const float* __restrict__ cw3, const float* __restrict__ fw3) {
    int idx = blockIdx.x * blockDim.x + threadIdx.x;
    if (idx >= PACK_TOT) return;
    if (idx < R0) {
        int row = idx >> 6, co = idx & 63;
        float v = 0.f;
        if (row < 256) {
            int kb = row >> 2, c = row & 3;
            if (co >= 32) v = __ldg(cw0 + (size_t)(kb * 4 + c) * 32 + (co - 32));
        } else if (row < 260) {
            int c = row - 256;
            if (co < 32) v = __ldg(fw0 + (size_t)c * 32 + co);
        }
        g_wb0[idx] = __float2half(v);
        if (idx < 64)
            g_bias0[idx] = (idx < 32) ? __ldg(fb0 + idx) : __ldg(cb0 + idx - 32);
        return;
    }
    idx -= R0;
    if (idx < R1) {
        int k = idx / NPAD, col = idx - k * NPAD;
        g_wc1[idx] = __float2half(wcat_val(cw1, fw1, k, col, 4160, 6, 63));
        if (idx < 64) g_bias1[idx] = __ldg(cb1 + idx) + __ldg(fb1 + idx);
        return;
    }
    idx -= R1;
    if (idx < R1) {
        int k = idx / NPAD, col = idx - k * NPAD;
        g_wc2[idx] = __float2half(wcat_val(cw2, fw2, k, col, 4160, 6, 63));
        if (idx < 64) g_bias2[idx] = __ldg(cb2 + idx) + __ldg(fb2 + idx);
        return;
    }
    idx -= R1;
    if (idx < R3) {
        int k = idx >> 8, col = idx & 255;
        g_wc3[idx] = __float2half(wcat_val(cw3, fw3, k, col, 130, 1, 1));
        return;
    }
    idx -= R3;
    g_cnt[idx] = 0;
}

// ---------------- edge preprocessing ----------------------------------------
__global__ void hist_kernel(const int* __restrict__ ei, int E) {
    int e = blockIdx.x * blockDim.x + threadIdx.x;
    if (e < E) g_rank[e] = atomicAdd(&g_cnt[__ldg(ei + e)], 1);
}

__global__ void scan1_kernel() {
    __shared__ int sh[1024];
    int b = blockIdx.x, tid = threadIdx.x;
    int idx = b * 1024 + tid;
    int v = (idx < NN) ? g_cnt[idx] : 0;
    sh[tid] = v;
    __syncthreads();
    for (int off = 512; off > 0; off >>= 1) {
        if (tid < off) sh[tid] += sh[tid + off];
        __syncthreads();
    }
    if (tid == 0) g_bsum[b] = sh[0];
}

__global__ void scan2_kernel() {
    __shared__ int sh[64];
    int tid = threadIdx.x;
    int v = (tid < SCAN_B) ? g_bsum[tid] : 0;
    sh[tid] = v;
    __syncthreads();
    for (int off = 1; off < 64; off <<= 1) {
        int t = (tid >= off) ? sh[tid - off] : 0;
        __syncthreads();
        sh[tid] += t;
        __syncthreads();
    }
    if (tid < SCAN_B) g_boff[tid] = sh[tid] - v;
    if (tid == SCAN_B - 1) g_boff[SCAN_B] = sh[tid];
}

__global__ void scan3_kernel() {
    __shared__ int sh[1024];
    int b = blockIdx.x, tid = threadIdx.x;
    int idx = b * 1024 + tid;
    int v = (idx < NN) ? g_cnt[idx] : 0;
    int orig = v;
    sh[tid] = v;
    __syncthreads();
    for (int off = 1; off < 1024; off <<= 1) {
        int t = (tid >= off) ? sh[tid - off] : 0;
        __syncthreads();
        sh[tid] += t;
        __syncthreads();
    }
    if (idx < NN)
        g_rowp[idx] = g_boff[b] + sh[tid] - orig;
    if (b == 0 && tid == 0) g_rowp[NN] = g_boff[SCAN_B];
}

__global__ void scatter_kernel(const float* __restrict__ pos,
                               const int* __restrict__ ei,
                               const int* __restrict__ ej, int E) {
    int e = blockIdx.x * blockDim.x + threadIdx.x;
    if (e >= E) return;
    int i = __ldg(ei + e), j = __ldg(ej + e);
    const float2* p2 = (const float2*)pos;
    float2 pi = __ldg(p2 + i);
    float2 pj = __ldg(p2 + j);
    float dx = pi.x - pj.x;
    float dy = pi.y - pj.y;
    dx = fminf(1.f, fmaxf(-1.f, dx));
    dy = fminf(1.f, fmaxf(-1.f, dy));
    uint32_t m = (i != j) ? 1u : 0u;
    float mf = (float)m;
    float r = sqrtf(dx * dx + dy * dy + 1e-12f);
    float u = fminf(1.f, fmaxf(-1.f, 2.f * r - 1.f));
    float v = atan2f(dy, dx) * 0.318309886183790672f;   // 1/pi
    float su = (u + 1.f) * 3.5f;
    int   iu = min(6, (int)floorf(su));
    float tu = su - (float)iu;
    float sv = (v + 1.f) * 3.5f;
    int   iv = min(6, (int)floorf(sv));
    float tv = sv - (float)iv;
    float w0 = (1.f - tu) * (1.f - tv) * mf;
    float w1 = (1.f - tu) * tv * mf;
    float w2 = tu * (1.f - tv) * mf;
    uint32_t kb = (uint32_t)(iu * 8 + iv);
    int p = g_rowp[i] + g_rank[e];
    uint4 ed;
    ed.x = (uint32_t)j | (kb << 20) | (m << 31);
    ed.y = __float_as_uint(w0);
    ed.z = __float_as_uint(w1);
    ed.w = __float_as_uint(w2);
    g_ed[p] = ed;
}

// ---------------- layer 0: moment accumulation (Cin=4) ----------------------
__global__ void mom0_kernel(const float* __restrict__ X) {
    __shared__ float M0s[8 * 256];
    int warp = threadIdx.x >> 5, lane = threadIdx.x & 31;
    int node = blockIdx.x * 8 + warp;
    float* M = M0s + warp * 256;
    #pragma unroll
    for (int r = 0; r < 8; r++) M[r * 32 + lane] = 0.f;
    __syncwarp();
    if (node < NN) {
        int e0 = g_rowp[node], e1 = g_rowp[node + 1];
        int t = lane >> 2, c = lane & 3;
        bool act = lane < 16;
        int kadd = (t & 1) + ((t >> 1) << 3);
        for (int e = e0; e < e1; e++) {
            uint4 ed = __ldg(&g_ed[e]);
            uint32_t jk = ed.x;
            int j = jk & 0xFFFFF;
            int kb = (jk >> 20) & 63;
            float w0 = __uint_as_float(ed.y);
            float w1 = __uint_as_float(ed.z);
            float w2 = __uint_as_float(ed.w);
            float w3 = (float)(jk >> 31) - w0 - w1 - w2;
            float4 xv = __ldg((const float4*)X + j);
            if (act) {
                float wt = (t == 0) ? w0 : (t == 1) ? w1 : (t == 2) ? w2 : w3;
                float xc = (c == 0) ? xv.x : (c == 1) ? xv.y : (c == 2) ? xv.z : xv.w;
                M[(kb + kadd) * 4 + c] += wt * xc;
            }
        }
        __syncwarp();
        __half* dst = g_m0 + (size_t)node * 320;
        #pragma unroll
        for (int r = 0; r < 4; r++) {
            int idx = r * 64 + 2 * lane;
            *(__half2*)(dst + idx) = __floats2half2_rn(M[idx], M[idx + 1]);
        }
        float4 xi = __ldg((const float4*)X + node);
        __half2 hv;
        if (lane == 0)      hv = __floats2half2_rn(xi.x, xi.y);
        else if (lane == 1) hv = __floats2half2_rn(xi.z, xi.w);
        else                hv = __floats2half2_rn(0.f, 0.f);
        *(__half2*)(dst + 256 + 2 * lane) = hv;
    }
}

// ---------------- layer 0 GEMM: ans0 = [M0|x] @ Wb0, bias, relu -> g_ah -----
#define GAST 72
__global__ void __launch_bounds__(256)
gemmA_kernel() {
    extern __shared__ __half smA[];
    __half* As = smA;                    // [128][GAST]
    __half* Bs = smA + 128 * GAST;       // [320][GAST]
    int m0 = blockIdx.x * 128;
    int tid = threadIdx.x;

    #pragma unroll
    for (int it = 0; it < 10; it++) {
        int idx = tid + it * 256;
        int row = idx >> 3;
        int c8 = idx & 7;
        uint4 v = __ldg((const uint4*)(g_wb0 + row * 64 + c8 * 8));
        *(uint4*)(Bs + row * GAST + c8 * 8) = v;
    }

    int warp = tid >> 5, lane = tid & 31;
    int wm = warp & 3, wn = warp >> 2;
    uint32_t asB = (uint32_t)__cvta_generic_to_shared(As);
    uint32_t bsB = (uint32_t)__cvta_generic_to_shared(Bs);

    float c[2][4][4];
    #pragma unroll
    for (int mi = 0; mi < 2; mi++)
        #pragma unroll
        for (int ni = 0; ni < 4; ni++)
            #pragma unroll
            for (int p = 0; p < 4; p++) c[mi][ni][p] = 0.f;

    for (int kc = 0; kc < 5; kc++) {
        __syncthreads();
        #pragma unroll
        for (int it = 0; it < 4; it++) {
            int idx = tid + it * 256;
            int row = idx >> 3;
            int c8 = idx & 7;
            uint4 v = make_uint4(0, 0, 0, 0);
            if (m0 + row < NN)
                v = __ldg((const uint4*)(g_m0 + (size_t)(m0 + row) * 320 + kc * 64 + c8 * 8));
            *(uint4*)(As + row * GAST + c8 * 8) = v;
        }
        __syncthreads();
        #pragma unroll
        for (int ks = 0; ks < 4; ks++) {
            int k0 = ks * 16;
            uint32_t a[2][4];
            #pragma unroll
            for (int mi = 0; mi < 2; mi++) {
                int row = wm * 32 + mi * 16 + (lane & 15);
                int col = k0 + ((lane >> 4) << 3);
                ldsm4(a[mi][0], a[mi][1], a[mi][2], a[mi][3],
                      asB + (row * GAST + col) * 2);
            }
            int brow = kc * 64 + k0 + (lane & 15);
            #pragma unroll
            for (int nq = 0; nq < 2; nq++) {
                int bcol = wn * 32 + nq * 16 + ((lane >> 4) << 3);
                uint32_t b0, b1, b2, b3;
                ldsm4t(b0, b1, b2, b3, bsB + (brow * GAST + bcol) * 2);
                #pragma unroll
                for (int mi = 0; mi < 2; mi++) {
                    mma16816(c[mi][nq * 2 + 0], a[mi], b0, b1);
                    mma16816(c[mi][nq * 2 + 1], a[mi], b2, b3);
                }
            }
        }
    }

    #pragma unroll
    for (int mi = 0; mi < 2; mi++) {
        #pragma unroll
        for (int ni = 0; ni < 4; ni++) {
            int row0 = m0 + wm * 32 + mi * 16 + (lane >> 2);
            int col = wn * 32 + ni * 8 + 2 * (lane & 3);
            float2 bv = *(const float2*)(g_bias0 + col);
            if (row0 < NN)
                *(__half2*)(g_ah + (size_t)row0 * 64 + col) = __floats2half2_rn(
                    fmaxf(c[mi][ni][0] + bv.x, 0.f), fmaxf(c[mi][ni][1] + bv.y, 0.f));
            int row1 = row0 + 8;
            if (row1 < NN)
                *(__half2*)(g_ah + (size_t)row1 * 64 + col) = __floats2half2_rn(
                    fmaxf(c[mi][ni][2] + bv.x, 0.f), fmaxf(c[mi][ni][3] + bv.y, 0.f));
        }
    }
}

// ---------------- persistent-A main GEMM: Y = Ah @ Wcat ---------------------
// per-warp private C staging -> only 2 block syncs per tile.
#define AST 72
#define BST 136
#define CWST 72
#define PSMEM ((128 * AST + 2 * 64 * BST + 8 * 32 * CWST) * 2)   // 90112 B

__global__ void __launch_bounds__(256, 2)
gemmP_kernel(const __half* __restrict__ wc, int wstride,
             int tilesPerSplit, int ntilesTot, int ystride) {
    extern __shared__ __half sp[];
    __half* As = sp;                                   // [128][AST]
    __half* Bs0 = sp + 128 * AST;                      // [64][BST] x2
    __half* CsW = sp + 128 * AST + 2 * 64 * BST;       // 8 x [32][CWST]
    int m0 = blockIdx.x * 128;
    int t0 = blockIdx.y * tilesPerSplit;
    int t1 = min(ntilesTot, t0 + tilesPerSplit);
    int tid = threadIdx.x;
    int warp = tid >> 5, lane = tid & 31;
    int wm = warp & 3, wn = warp >> 2;
    __half* Cw = CsW + warp * 32 * CWST;

    // stage A once
    #pragma unroll
    for (int it = 0; it < 4; it++) {
        int idx = tid + it * 256;
        int row = idx >> 3;
        int c8 = idx & 7;
        uint4 v = make_uint4(0, 0, 0, 0);
        if (m0 + row < NN)
            v = __ldg((const uint4*)(g_ah + (size_t)(m0 + row) * 64 + c8 * 8));
        *(uint4*)(As + row * AST + c8 * 8) = v;
    }

    auto loadB = [&](int buf, int t) {
        uint32_t bb = (uint32_t)__cvta_generic_to_shared(Bs0 + buf * 64 * BST);
        int n0 = t * 128;
        #pragma unroll
        for (int it = 0; it < 4; it++) {
            int idx = tid + it * 256;      // 1024 x 16B
            int row = idx >> 4;
            int c8 = idx & 15;
            cpa16(bb + (row * BST + c8 * 8) * 2,
                  wc + (size_t)row * wstride + n0 + c8 * 8);
        }
        CP_COMMIT();
    };

    uint32_t asBase = (uint32_t)__cvta_generic_to_shared(As);
    loadB(0, t0);

    for (int t = t0; t < t1; t++) {
        int buf = (t - t0) & 1;
        if (t + 1 < t1) loadB(buf ^ 1, t + 1);
        if (t + 1 < t1) { CP_WAIT1(); } else { CP_WAIT0(); }
        __syncthreads();                               // S1: B(t) visible (+A first iter)

        uint32_t bsBase = (uint32_t)__cvta_generic_to_shared(Bs0 + buf * 64 * BST);
        float c[2][8][4];
        #pragma unroll
        for (int mi = 0; mi < 2; mi++)
            #pragma unroll
            for (int ni = 0; ni < 8; ni++)
                #pragma unroll
                for (int p = 0; p < 4; p++) c[mi][ni][p] = 0.f;

        #pragma unroll
        for (int ks = 0; ks < 4; ks++) {
            int k0 = ks * 16;
            uint32_t a[2][4];
            #pragma unroll
            for (int mi = 0; mi < 2; mi++) {
                int row = wm * 32 + mi * 16 + (lane & 15);
                int col = k0 + ((lane >> 4) << 3);
                ldsm4(a[mi][0], a[mi][1], a[mi][2], a[mi][3],
                      asBase + (row * AST + col) * 2);
            }
            #pragma unroll
            for (int nq = 0; nq < 4; nq++) {
                int row = k0 + (lane & 15);
                int col = wn * 64 + nq * 16 + ((lane >> 4) << 3);
                uint32_t b0, b1, b2, b3;
                ldsm4t(b0, b1, b2, b3, bsBase + (row * BST + col) * 2);
                #pragma unroll
                for (int mi = 0; mi < 2; mi++) {
                    mma16816(c[mi][nq * 2 + 0], a[mi], b0, b1);
                    mma16816(c[mi][nq * 2 + 1], a[mi], b2, b3);
                }
            }
        }
        __syncthreads();                               // S2: all mma(t) done -> buf reuse safe

        // per-warp epilogue: fragments -> private Cs slice -> 128B row stores
        #pragma unroll
        for (int mi = 0; mi < 2; mi++) {
            #pragma unroll
            for (int ni = 0; ni < 8; ni++) {
                int r0 = mi * 16 + (lane >> 2);
                int col = ni * 8 + 2 * (lane & 3);
                *(__half2*)(Cw + r0 * CWST + col) =
                    __floats2half2_rn(c[mi][ni][0], c[mi][ni][1]);
                *(__half2*)(Cw + (r0 + 8) * CWST + col) =
                    __floats2half2_rn(c[mi][ni][2], c[mi][ni][3]);
            }
        }
        __syncwarp();
        int n0 = t * 128 + wn * 64;
        #pragma unroll
        for (int p = 0; p < 8; p++) {
            int row = p * 4 + (lane >> 3);
            int gr = m0 + wm * 32 + row;
            if (gr < NN) {
                uint4 v = *(const uint4*)(Cw + row * CWST + (lane & 7) * 8);
                *(uint4*)(g_y + (size_t)gr * ystride + n0 + (lane & 7) * 8) = v;
            }
        }
        __syncwarp();
    }
}

// ---------------- gather for 64-wide layers (half2, dual accumulators) ------
template <bool RES, bool WF32>
__global__ void gather64_kernel(const float* __restrict__ bias,
                                const float* __restrict__ resid,
                                float* __restrict__ outF) {
    int warpId = (blockIdx.x * blockDim.x + threadIdx.x) >> 5;
    int lane = threadIdx.x & 31;
    if (warpId >= NN) return;
    int i = warpId;
    int e0 = g_rowp[i], e1 = g_rowp[i + 1];
    float2 accA = make_float2(0.f, 0.f);
    float2 accB = make_float2(0.f, 0.f);
    int e = e0;
    for (; e + 1 < e1; e += 2) {
        uint4 ed0 = __ldg(&g_ed[e]);
        uint4 ed1 = __ldg(&g_ed[e + 1]);
        {
            uint32_t jk = ed0.x;
            int j = jk & 0xFFFFF, kb = (jk >> 20) & 63;
            float w0 = __uint_as_float(ed0.y);
            float w1 = __uint_as_float(ed0.z);
            float w2 = __uint_as_float(ed0.w);
            float w3 = (float)(jk >> 31) - w0 - w1 - w2;
            const __half2* r = (const __half2*)(g_y + (size_t)j * YS1 + kb * 64 + 2 * lane);
            float2 f0 = __half22float2(__ldg(r));
            float2 f1 = __half22float2(__ldg(r + 32));
            float2 f2 = __half22float2(__ldg(r + 256));
            float2 f3 = __half22float2(__ldg(r + 288));
            accA.x += w0 * f0.x + w1 * f1.x + w2 * f2.x + w3 * f3.x;
            accA.y += w0 * f0.y + w1 * f1.y + w2 * f2.y + w3 * f3.y;
        }
        {
            uint32_t jk = ed1.x;
            int j = jk & 0xFFFFF, kb = (jk >> 20) & 63;
            float w0 = __uint_as_float(ed1.y);
            float w1 = __uint_as_float(ed1.z);
            float w2 = __uint_as_float(ed1.w);
            float w3 = (float)(jk >> 31) - w0 - w1 - w2;
            const __half2* r = (const __half2*)(g_y + (size_t)j * YS1 + kb * 64 + 2 * lane);
            float2 f0 = __half22float2(__ldg(r));
            float2 f1 = __half22float2(__ldg(r + 32));
            float2 f2 = __half22float2(__ldg(r + 256));
            float2 f3 = __half22float2(__ldg(r + 288));
            accB.x += w0 * f0.x + w1 * f1.x + w2 * f2.x + w3 * f3.x;
            accB.y += w0 * f0.y + w1 * f1.y + w2 * f2.y + w3 * f3.y;
        }
    }
    if (e < e1) {
        uint4 ed0 = __ldg(&g_ed[e]);
        uint32_t jk = ed0.x;
        int j = jk & 0xFFFFF, kb = (jk >> 20) & 63;
        float w0 = __uint_as_float(ed0.y);
        float w1 = __uint_as_float(ed0.z);
        float w2 = __uint_as_float(ed0.w);
        float w3 = (float)(jk >> 31) - w0 - w1 - w2;
        const __half2* r = (const __half2*)(g_y + (size_t)j * YS1 + kb * 64 + 2 * lane);
        float2 f0 = __half22float2(__ldg(r));
        float2 f1 = __half22float2(__ldg(r + 32));
        float2 f2 = __half22float2(__ldg(r + 256));
        float2 f3 = __half22float2(__ldg(r + 288));
        accA.x += w0 * f0.x + w1 * f1.x + w2 * f2.x + w3 * f3.x;
        accA.y += w0 * f0.y + w1 * f1.y + w2 * f2.y + w3 * f3.y;
    }
    float2 acc = make_float2(accA.x + accB.x, accA.y + accB.y);
    float2 s = __half22float2(*(const __half2*)(g_y + (size_t)i * YS1 + 4096 + 2 * lane));
    float2 bv = *(const float2*)(bias + 2 * lane);
    float2 o = make_float2(acc.x + s.x + bv.x, acc.y + s.y + bv.y);
    if (RES) {
        float2 rv = *(const float2*)(resid + (size_t)i * 64 + 2 * lane);
        o.x += rv.x; o.y += rv.y;
    }
    if (WF32)
        *(float2*)(outF + (size_t)i * 64 + 2 * lane) = o;
    *(__half2*)(g_ah + (size_t)i * 64 + 2 * lane) =
        __floats2half2_rn(fmaxf(o.x, 0.f), fmaxf(o.y, 0.f));
}

// ---------------- final gather (Cout = 2) + /128 ----------------------------
__global__ void gatherF_kernel(const float* __restrict__ cb3,
                               const float* __restrict__ fb3,
                               float* __restrict__ out) {
    int warpId = (blockIdx.x * blockDim.x + threadIdx.x) >> 5;
    int lane = threadIdx.x & 31;
    if (warpId >= NN) return;
    int i = warpId;
    int e0 = g_rowp[i], e1 = g_rowp[i + 1];
    float accx = 0.f, accy = 0.f;
    for (int e = e0 + lane; e < e1; e += 32) {
        uint4 ed = __ldg(&g_ed[e]);
        uint32_t jk = ed.x;
        int j = jk & 0xFFFFF, kb = (jk >> 20) & 63;
        float w0 = __uint_as_float(ed.y);
        float w1 = __uint_as_float(ed.z);
        float w2 = __uint_as_float(ed.w);
        float w3 = (float)(jk >> 31) - w0 - w1 - w2;
        const __half2* r = (const __half2*)(g_y + (size_t)j * YS3 + kb * 2);
        float2 f0 = __half22float2(__ldg(r));
        float2 f1 = __half22float2(__ldg(r + 1));
        float2 f2 = __half22float2(__ldg(r + 8));
        float2 f3 = __half22float2(__ldg(r + 9));
        accx += w0 * f0.x + w1 * f1.x + w2 * f2.x + w3 * f3.x;
        accy += w0 * f0.y + w1 * f1.y + w2 * f2.y + w3 * f3.y;
    }
    #pragma unroll
    for (int off = 16; off > 0; off >>= 1) {
        accx += __shfl_down_sync(0xFFFFFFFFu, accx, off);
        accy += __shfl_down_sync(0xFFFFFFFFu, accy, off);
    }
    if (lane == 0) {
        float2 ds = __half22float2(*(const __half2*)(g_y + (size_t)i * YS3 + 128));
        out[2 * i]     = (accx + ds.x + cb3[0] + fb3[0]) * (1.f / 128.f);
        out[2 * i + 1] = (accy + ds.y + cb3[1] + fb3[1]) * (1.f / 128.f);
    }
}

// ---------------- launch ----------------------------------------------------
extern "C" void kernel_launch(void* const* d_in, const int* in_sizes, int n_in,
                              void* d_out, int out_size) {
    const float* pos  = (const float*)d_in[0];
    const float* feat = (const float*)d_in[1];
    const int*   ei   = (const int*)d_in[2];
    const int*   ej   = (const int*)d_in[3];
    const float* cw0 = (const float*)d_in[4];
    const float* cb0 = (const float*)d_in[5];
    const float* fw0 = (const float*)d_in[6];
    const float* fb0 = (const float*)d_in[7];
    const float* cw1 = (const float*)d_in[8];
    const float* cb1 = (const float*)d_in[9];
    const float* fw1 = (const float*)d_in[10];
    const float* fb1 = (const float*)d_in[11];
    const float* cw2 = (const float*)d_in[12];
    const float* cb2 = (const float*)d_in[13];
    const float* fw2 = (const float*)d_in[14];
    const float* fb2 = (const float*)d_in[15];
    const float* cw3 = (const float*)d_in[16];
    const float* cb3 = (const float*)d_in[17];
    const float* fw3 = (const float*)d_in[18];
    const float* fb3 = (const float*)d_in[19];
    float* out = (float*)d_out;
    int E = in_sizes[2];

    const int SMEMA = (128 * GAST + 320 * GAST) * 2;   // 64512 B
    cudaFuncSetAttribute(gemmA_kernel,
                         cudaFuncAttributeMaxDynamicSharedMemorySize, SMEMA);
    cudaFuncSetAttribute(gemmP_kernel,
                         cudaFuncAttributeMaxDynamicSharedMemorySize, PSMEM);

    float* aF;  cudaGetSymbolAddress((void**)&aF, g_ansF);
    __half* w1; cudaGetSymbolAddress((void**)&w1, g_wc1);
    __half* w2; cudaGetSymbolAddress((void**)&w2, g_wc2);
    __half* w3; cudaGetSymbolAddress((void**)&w3, g_wc3);
    float* b1;  cudaGetSymbolAddress((void**)&b1, g_bias1);
    float* b2;  cudaGetSymbolAddress((void**)&b2, g_bias2);

    // all weight packing + cnt zero in one launch
    packAll_kernel<<<(PACK_TOT + 255) / 256, 256>>>(
        cw0, fw0, cb0, fb0, cw1, fw1, cb1, fb1,
        cw2, fw2, cb2, fb2, cw3, fw3);

    // edge counting sort (single atomic pass)
    hist_kernel<<<(E + 255) / 256, 256>>>(ei, E);
    scan1_kernel<<<SCAN_B, 1024>>>();
    scan2_kernel<<<1, 64>>>();
    scan3_kernel<<<SCAN_B, 1024>>>();
    scatter_kernel<<<(E + 255) / 256, 256>>>(pos, ei, ej, E);

    // layer 0 (moment formulation)
    mom0_kernel<<<NN / 8, 256>>>(feat);
    gemmA_kernel<<<391, 256, SMEMA>>>();

    // layer 1
    gemmP_kernel<<<dim3(391, 3), 256, PSMEM>>>(w1, NPAD, 11, 33, YS1);
    gather64_kernel<false, true><<<(NN * 32 + 255) / 256, 256>>>(b1, nullptr, aF);

    // layer 2 (residual = ansF)
    gemmP_kernel<<<dim3(391, 3), 256, PSMEM>>>(w2, NPAD, 11, 33, YS1);
    gather64_kernel<true, false><<<(NN * 32 + 255) / 256, 256>>>(b2, aF, nullptr);

    // layer 3
    gemmP_kernel<<<dim3(391, 1), 256, PSMEM>>>(w3, 256, 2, 2, YS3);
    gatherF_kernel<<<(NN * 32 + 255) / 256, 256>>>(cb3, fb3, out);
}

// round 13
// speedup vs baseline: 2.5915x; 1.1160x over previous
#include <cuda_runtime.h>
#include <cuda_fp16.h>
#include <stdint.h>

#define NN 50000
#define EE 1600000
#define YS1 4224          // padded y stride (halves) for 64->64 layers (33*128)
#define YS3 256           // y stride for layer3
#define NPAD 4224         // packed-weight column pad (layers 1/2)
#define SCAN_B 49         // ceil(50000/1024)

// ---------------- device scratch (no runtime allocation allowed) ------------
__device__ __align__(16) __half g_y[(size_t)NN * YS1];   // 422 MB
__device__ __align__(16) __half g_wc1[64 * NPAD];
__device__ __align__(16) __half g_wc2[64 * NPAD];
__device__ __align__(16) __half g_wc3[64 * 256];
__device__ __align__(16) __half g_ah[NN * 64];           // relu(ans) fp16 (GEMM A)
__device__ __align__(16) float  g_ansF[NN * 64];         // layer1 out fp32 (residual)
__device__ __align__(16) __half g_m0[(size_t)NN * 320];  // layer0 moments + x, fp16
__device__ __align__(16) __half g_wb0[320 * 64];         // layer0 packed weights
__device__ float  g_bias0[64];
__device__ float  g_bias1[64];
__device__ float  g_bias2[64];
__device__ int    g_cnt[NN + 1];
__device__ int    g_rowp[NN + 1];
__device__ int    g_rank[EE];
__device__ int    g_bsum[SCAN_B];
__device__ int    g_boff[SCAN_B + 1];
// edge record: .x = j | kb<<20 | m<<31 ; .y/.z/.w = w0,w1,w2 (fp32 bits)
__device__ __align__(16) uint4 g_ed[EE];

// ---------------- mma / async helpers ----------------------------------------
__device__ __forceinline__ void ldsm4(uint32_t& r0, uint32_t& r1, uint32_t& r2,
                                      uint32_t& r3, uint32_t addr) {
    asm volatile("ldmatrix.sync.aligned.m8n8.x4.shared.b16 {%0,%1,%2,%3}, [%4];"
                 : "=r"(r0), "=r"(r1), "=r"(r2), "=r"(r3) : "r"(addr));
}
__device__ __forceinline__ void ldsm4t(uint32_t& r0, uint32_t& r1, uint32_t& r2,
                                       uint32_t& r3, uint32_t addr) {
    asm volatile("ldmatrix.sync.aligned.m8n8.x4.trans.shared.b16 {%0,%1,%2,%3}, [%4];"
                 : "=r"(r0), "=r"(r1), "=r"(r2), "=r"(r3) : "r"(addr));
}
__device__ __forceinline__ void mma16816(float* c, const uint32_t* a,
                                         uint32_t b0, uint32_t b1) {
    asm volatile(
        "mma.sync.aligned.m16n8k16.row.col.f32.f16.f16.f32 "
        "{%0,%1,%2,%3}, {%4,%5,%6,%7}, {%8,%9}, {%0,%1,%2,%3};"
        : "+f"(c[0]), "+f"(c[1]), "+f"(c[2]), "+f"(c[3])
        : "r"(a[0]), "r"(a[1]), "r"(a[2]), "r"(a[3]), "r"(b0), "r"(b1));
}
__device__ __forceinline__ void cpa16(uint32_t dst, const void* src) {
    asm volatile("cp.async.cg.shared.global [%0], [%1], 16;" :: "r"(dst), "l"(src));
}
__device__ __forceinline__ void cpa16z(uint32_t dst, const void* src, int nbytes) {
    asm volatile("cp.async.cg.shared.global [%0], [%1], 16, %2;"
                 :: "r"(dst), "l"(src), "r"(nbytes));
}
#define CP_COMMIT() asm volatile("cp.async.commit_group;")
#define CP_WAIT0()  asm volatile("cp.async.wait_group 0;")

// ---------------- combined weight pack + cnt zero ----------------------------
#define R0 (320 * 64)
#define R1 (64 * NPAD)
#define R3 (64 * 256)
#define PACK_TOT (R0 + 2 * R1 + R3 + NN + 1)

__device__ __forceinline__ float wcat_val(const float* CW, const float* FW,
                                          int k, int col, int ncols,
                                          int coutShift, int coutMask) {
    if (col >= ncols) return 0.f;
    int cout = 1 << coutShift;
    int kcoutTot = 64 << coutShift;
    if (col < kcoutTot) {
        int kk = col >> coutShift;
        int co = col & coutMask;
        return __ldg(CW + (size_t)(kk * 64 + k) * cout + co);
    }
    return __ldg(FW + (size_t)k * cout + (col - kcoutTot));
}

__global__ void packAll_kernel(
    const float* __restrict__ cw0, const float* __restrict__ fw0,
    const float* __restrict__ cb0, const float* __restrict__ fb0,
    const float* __restrict__ cw1, const float* __restrict__ fw1,
    const float* __restrict__ cb1, const float* __restrict__ fb1,
    const float* __restrict__ cw2, const float* __restrict__ fw2,
    const float* __restrict__ cb2, const float* __restrict__ fb2,
    const float* __restrict__ cw3, const float* __restrict__ fw3) {
    int idx = blockIdx.x * blockDim.x + threadIdx.x;
    if (idx >= PACK_TOT) return;
    if (idx < R0) {
        int row = idx >> 6, co = idx & 63;
        float v = 0.f;
        if (row < 256) {
            int kb = row >> 2, c = row & 3;
            if (co >= 32) v = __ldg(cw0 + (size_t)(kb * 4 + c) * 32 + (co - 32));
        } else if (row < 260) {
            int c = row - 256;
            if (co < 32) v = __ldg(fw0 + (size_t)c * 32 + co);
        }
        g_wb0[idx] = __float2half(v);
        if (idx < 64)
            g_bias0[idx] = (idx < 32) ? __ldg(fb0 + idx) : __ldg(cb0 + idx - 32);
        return;
    }
    idx -= R0;
    if (idx < R1) {
        int k = idx / NPAD, col = idx - k * NPAD;
        g_wc1[idx] = __float2half(wcat_val(cw1, fw1, k, col, 4160, 6, 63));
        if (idx < 64) g_bias1[idx] = __ldg(cb1 + idx) + __ldg(fb1 + idx);
        return;
    }
    idx -= R1;
    if (idx < R1) {
        int k = idx / NPAD, col = idx - k * NPAD;
        g_wc2[idx] = __float2half(wcat_val(cw2, fw2, k, col, 4160, 6, 63));
        if (idx < 64) g_bias2[idx] = __ldg(cb2 + idx) + __ldg(fb2 + idx);
        return;
    }
    idx -= R1;
    if (idx < R3) {
        int k = idx >> 8, col = idx & 255;
        g_wc3[idx] = __float2half(wcat_val(cw3, fw3, k, col, 130, 1, 1));
        return;
    }
    idx -= R3;
    g_cnt[idx] = 0;
}

// ---------------- edge preprocessing ----------------------------------------
__global__ void hist_kernel(const int* __restrict__ ei, int E) {
    int e = blockIdx.x * blockDim.x + threadIdx.x;
    if (e < E) g_rank[e] = atomicAdd(&g_cnt[__ldg(ei + e)], 1);
}

__global__ void scan1_kernel() {
    __shared__ int sh[1024];
    int b = blockIdx.x, tid = threadIdx.x;
    int idx = b * 1024 + tid;
    int v = (idx < NN) ? g_cnt[idx] : 0;
    sh[tid] = v;
    __syncthreads();
    for (int off = 512; off > 0; off >>= 1) {
        if (tid < off) sh[tid] += sh[tid + off];
        __syncthreads();
    }
    if (tid == 0) g_bsum[b] = sh[0];
}

__global__ void scan2_kernel() {
    __shared__ int sh[64];
    int tid = threadIdx.x;
    int v = (tid < SCAN_B) ? g_bsum[tid] : 0;
    sh[tid] = v;
    __syncthreads();
    for (int off = 1; off < 64; off <<= 1) {
        int t = (tid >= off) ? sh[tid - off] : 0;
        __syncthreads();
        sh[tid] += t;
        __syncthreads();
    }
    if (tid < SCAN_B) g_boff[tid] = sh[tid] - v;
    if (tid == SCAN_B - 1) g_boff[SCAN_B] = sh[tid];
}

__global__ void scan3_kernel() {
    __shared__ int sh[1024];
    int b = blockIdx.x, tid = threadIdx.x;
    int idx = b * 1024 + tid;
    int v = (idx < NN) ? g_cnt[idx] : 0;
    int orig = v;
    sh[tid] = v;
    __syncthreads();
    for (int off = 1; off < 1024; off <<= 1) {
        int t = (tid >= off) ? sh[tid - off] : 0;
        __syncthreads();
        sh[tid] += t;
        __syncthreads();
    }
    if (idx < NN)
        g_rowp[idx] = g_boff[b] + sh[tid] - orig;
    if (b == 0 && tid == 0) g_rowp[NN] = g_boff[SCAN_B];
}

__global__ void scatter_kernel(const float* __restrict__ pos,
                               const int* __restrict__ ei,
                               const int* __restrict__ ej, int E) {
    int e = blockIdx.x * blockDim.x + threadIdx.x;
    if (e >= E) return;
    int i = __ldg(ei + e), j = __ldg(ej + e);
    const float2* p2 = (const float2*)pos;
    float2 pi = __ldg(p2 + i);
    float2 pj = __ldg(p2 + j);
    float dx = pi.x - pj.x;
    float dy = pi.y - pj.y;
    dx = fminf(1.f, fmaxf(-1.f, dx));
    dy = fminf(1.f, fmaxf(-1.f, dy));
    uint32_t m = (i != j) ? 1u : 0u;
    float mf = (float)m;
    float r = sqrtf(dx * dx + dy * dy + 1e-12f);
    float u = fminf(1.f, fmaxf(-1.f, 2.f * r - 1.f));
    float v = atan2f(dy, dx) * 0.318309886183790672f;   // 1/pi
    float su = (u + 1.f) * 3.5f;
    int   iu = min(6, (int)floorf(su));
    float tu = su - (float)iu;
    float sv = (v + 1.f) * 3.5f;
    int   iv = min(6, (int)floorf(sv));
    float tv = sv - (float)iv;
    float w0 = (1.f - tu) * (1.f - tv) * mf;
    float w1 = (1.f - tu) * tv * mf;
    float w2 = tu * (1.f - tv) * mf;
    uint32_t kb = (uint32_t)(iu * 8 + iv);
    int p = g_rowp[i] + g_rank[e];
    uint4 ed;
    ed.x = (uint32_t)j | (kb << 20) | (m << 31);
    ed.y = __float_as_uint(w0);
    ed.z = __float_as_uint(w1);
    ed.w = __float_as_uint(w2);
    g_ed[p] = ed;
}

// ---------------- layer 0: moment accumulation (dual-edge, Cin=4) -----------
__global__ void mom0_kernel(const float* __restrict__ X) {
    __shared__ float M0s[8 * 512];
    int warp = threadIdx.x >> 5, lane = threadIdx.x & 31;
    int node = blockIdx.x * 8 + warp;
    float* M = M0s + warp * 512;
    #pragma unroll
    for (int r = 0; r < 16; r++) M[r * 32 + lane] = 0.f;
    __syncwarp();
    if (node < NN) {
        int e0 = g_rowp[node], e1 = g_rowp[node + 1];
        int p = lane >> 4;                 // edge parity
        int t = (lane >> 2) & 3;           // tap
        int c = lane & 3;                  // channel
        int kadd = (t & 1) + ((t >> 1) << 3);
        float* Mp = M + p * 256;
        for (int e = e0; e < e1; e += 2) {
            int ee = e + p;
            if (ee < e1) {
                uint4 ed = __ldg(&g_ed[ee]);
                uint32_t jk = ed.x;
                int j = jk & 0xFFFFF;
                int kb = (jk >> 20) & 63;
                float w0 = __uint_as_float(ed.y);
                float w1 = __uint_as_float(ed.z);
                float w2 = __uint_as_float(ed.w);
                float w3 = (float)(jk >> 31) - w0 - w1 - w2;
                float4 xv = __ldg((const float4*)X + j);
                float wt = (t == 0) ? w0 : (t == 1) ? w1 : (t == 2) ? w2 : w3;
                float xc = (c == 0) ? xv.x : (c == 1) ? xv.y : (c == 2) ? xv.z : xv.w;
                Mp[(kb + kadd) * 4 + c] += wt * xc;
            }
        }
        __syncwarp();
        __half* dst = g_m0 + (size_t)node * 320;
        #pragma unroll
        for (int r = 0; r < 4; r++) {
            int idx = r * 64 + 2 * lane;
            float v0 = M[idx] + M[256 + idx];
            float v1 = M[idx + 1] + M[256 + idx + 1];
            *(__half2*)(dst + idx) = __floats2half2_rn(v0, v1);
        }
        float4 xi = __ldg((const float4*)X + node);
        __half2 hv;
        if (lane == 0)      hv = __floats2half2_rn(xi.x, xi.y);
        else if (lane == 1) hv = __floats2half2_rn(xi.z, xi.w);
        else                hv = __floats2half2_rn(0.f, 0.f);
        *(__half2*)(dst + 256 + 2 * lane) = hv;
    }
}

// ---------------- layer 0 GEMM: ans0 = [M0|x] @ Wb0, bias, relu -> g_ah -----
#define GAST 72
#define SMEMA ((2 * 128 * GAST + 320 * GAST) * 2)   // 82944 B

__global__ void __launch_bounds__(256)
gemmA_kernel() {
    extern __shared__ __half smA[];
    __half* Ab0 = smA;
    __half* Ab1 = smA + 128 * GAST;
    __half* Bs = smA + 2 * 128 * GAST;   // [320][GAST]
    int m0 = blockIdx.x * 128;
    int tid = threadIdx.x;

    // stage B (plain stores; first __syncthreads covers visibility)
    #pragma unroll
    for (int it = 0; it < 10; it++) {
        int idx = tid + it * 256;
        int row = idx >> 3;
        int c8 = idx & 7;
        uint4 v = __ldg((const uint4*)(g_wb0 + row * 64 + c8 * 8));
        *(uint4*)(Bs + row * GAST + c8 * 8) = v;
    }

    auto loadA = [&](__half* dst, int kc) {
        uint32_t ab = (uint32_t)__cvta_generic_to_shared(dst);
        #pragma unroll
        for (int it = 0; it < 4; it++) {
            int idx = tid + it * 256;
            int row = idx >> 3;
            int c8 = idx & 7;
            int nb = (m0 + row < NN) ? 16 : 0;
            cpa16z(ab + (row * GAST + c8 * 8) * 2,
                   g_m0 + (size_t)(m0 + row) * 320 + kc * 64 + c8 * 8, nb);
        }
        CP_COMMIT();
    };

    int warp = tid >> 5, lane = tid & 31;
    int wm = warp & 3, wn = warp >> 2;
    uint32_t bsB = (uint32_t)__cvta_generic_to_shared(Bs);

    float c[2][4][4];
    #pragma unroll
    for (int mi = 0; mi < 2; mi++)
        #pragma unroll
        for (int ni = 0; ni < 4; ni++)
            #pragma unroll
            for (int p = 0; p < 4; p++) c[mi][ni][p] = 0.f;

    loadA(Ab0, 0);
    for (int kc = 0; kc < 5; kc++) {
        CP_WAIT0();
        __syncthreads();
        if (kc < 4) loadA((kc & 1) ? Ab0 : Ab1, kc + 1);
        uint32_t asB = (uint32_t)__cvta_generic_to_shared((kc & 1) ? Ab1 : Ab0);
        #pragma unroll
        for (int ks = 0; ks < 4; ks++) {
            int k0 = ks * 16;
            uint32_t a[2][4];
            #pragma unroll
            for (int mi = 0; mi < 2; mi++) {
                int row = wm * 32 + mi * 16 + (lane & 15);
                int col = k0 + ((lane >> 4) << 3);
                ldsm4(a[mi][0], a[mi][1], a[mi][2], a[mi][3],
                      asB + (row * GAST + col) * 2);
            }
            int brow = kc * 64 + k0 + (lane & 15);
            #pragma unroll
            for (int nq = 0; nq < 2; nq++) {
                int bcol = wn * 32 + nq * 16 + ((lane >> 4) << 3);
                uint32_t b0, b1, b2, b3;
                ldsm4t(b0, b1, b2, b3, bsB + (brow * GAST + bcol) * 2);
                #pragma unroll
                for (int mi = 0; mi < 2; mi++) {
                    mma16816(c[mi][nq * 2 + 0], a[mi], b0, b1);
                    mma16816(c[mi][nq * 2 + 1], a[mi], b2, b3);
                }
            }
        }
    }

    #pragma unroll
    for (int mi = 0; mi < 2; mi++) {
        #pragma unroll
        for (int ni = 0; ni < 4; ni++) {
            int row0 = m0 + wm * 32 + mi * 16 + (lane >> 2);
            int col = wn * 32 + ni * 8 + 2 * (lane & 3);
            float2 bv = *(const float2*)(g_bias0 + col);
            if (row0 < NN)
                *(__half2*)(g_ah + (size_t)row0 * 64 + col) = __floats2half2_rn(
                    fmaxf(c[mi][ni][0] + bv.x, 0.f), fmaxf(c[mi][ni][1] + bv.y, 0.f));
            int row1 = row0 + 8;
            if (row1 < NN)
                *(__half2*)(g_ah + (size_t)row1 * 64 + col) = __floats2half2_rn(
                    fmaxf(c[mi][ni][2] + bv.x, 0.f), fmaxf(c[mi][ni][3] + bv.y, 0.f));
        }
    }
}

// ---------------- persistent-A main GEMM: Y = Ah @ Wcat ---------------------
// ONE block barrier per tile: loadB(t+1) issued after the barrier, into the
// buffer freed by mma(t-1) (all warps provably past it).
#define AST 72
#define BST 136
#define CWST 72
#define PSMEM ((128 * AST + 2 * 64 * BST + 8 * 32 * CWST) * 2)   // 90112 B

__global__ void __launch_bounds__(256, 2)
gemmP_kernel(const __half* __restrict__ wc, int wstride,
             int tilesPerSplit, int ntilesTot, int ystride) {
    extern __shared__ __half sp[];
    __half* As = sp;                                   // [128][AST]
    __half* Bs0 = sp + 128 * AST;                      // [64][BST] x2
    __half* CsW = sp + 128 * AST + 2 * 64 * BST;       // 8 x [32][CWST]
    int m0 = blockIdx.x * 128;
    int t0 = blockIdx.y * tilesPerSplit;
    int t1 = min(ntilesTot, t0 + tilesPerSplit);
    int tid = threadIdx.x;
    int warp = tid >> 5, lane = tid & 31;
    int wm = warp & 3, wn = warp >> 2;
    __half* Cw = CsW + warp * 32 * CWST;

    // stage A once (plain stores; covered by first barrier)
    #pragma unroll
    for (int it = 0; it < 4; it++) {
        int idx = tid + it * 256;
        int row = idx >> 3;
        int c8 = idx & 7;
        uint4 v = make_uint4(0, 0, 0, 0);
        if (m0 + row < NN)
            v = __ldg((const uint4*)(g_ah + (size_t)(m0 + row) * 64 + c8 * 8));
        *(uint4*)(As + row * AST + c8 * 8) = v;
    }

    auto loadB = [&](int buf, int t) {
        uint32_t bb = (uint32_t)__cvta_generic_to_shared(Bs0 + buf * 64 * BST);
        int n0 = t * 128;
        #pragma unroll
        for (int it = 0; it < 4; it++) {
            int idx = tid + it * 256;      // 1024 x 16B
            int row = idx >> 4;
            int c8 = idx & 15;
            cpa16(bb + (row * BST + c8 * 8) * 2,
                  wc + (size_t)row * wstride + n0 + c8 * 8);
        }
        CP_COMMIT();
    };

    uint32_t asBase = (uint32_t)__cvta_generic_to_shared(As);
    loadB(0, t0);

    for (int t = t0; t < t1; t++) {
        int buf = (t - t0) & 1;
        CP_WAIT0();                                    // B(t) landed
        __syncthreads();                               // all warps past mma(t-1)
        if (t + 1 < t1) loadB(buf ^ 1, t + 1);         // into freed buffer

        uint32_t bsBase = (uint32_t)__cvta_generic_to_shared(Bs0 + buf * 64 * BST);
        float c[2][8][4];
        #pragma unroll
        for (int mi = 0; mi < 2; mi++)
            #pragma unroll
            for (int ni = 0; ni < 8; ni++)
                #pragma unroll
                for (int p = 0; p < 4; p++) c[mi][ni][p] = 0.f;

        #pragma unroll
        for (int ks = 0; ks < 4; ks++) {
            int k0 = ks * 16;
            uint32_t a[2][4];
            #pragma unroll
            for (int mi = 0; mi < 2; mi++) {
                int row = wm * 32 + mi * 16 + (lane & 15);
                int col = k0 + ((lane >> 4) << 3);
                ldsm4(a[mi][0], a[mi][1], a[mi][2], a[mi][3],
                      asBase + (row * AST + col) * 2);
            }
            #pragma unroll
            for (int nq = 0; nq < 4; nq++) {
                int row = k0 + (lane & 15);
                int col = wn * 64 + nq * 16 + ((lane >> 4) << 3);
                uint32_t b0, b1, b2, b3;
                ldsm4t(b0, b1, b2, b3, bsBase + (row * BST + col) * 2);
                #pragma unroll
                for (int mi = 0; mi < 2; mi++) {
                    mma16816(c[mi][nq * 2 + 0], a[mi], b0, b1);
                    mma16816(c[mi][nq * 2 + 1], a[mi], b2, b3);
                }
            }
        }

        // per-warp epilogue: fragments -> private Cs slice -> 128B row stores
        #pragma unroll
        for (int mi = 0; mi < 2; mi++) {
            #pragma unroll
            for (int ni = 0; ni < 8; ni++) {
                int r0 = mi * 16 + (lane >> 2);
                int col = ni * 8 + 2 * (lane & 3);
                *(__half2*)(Cw + r0 * CWST + col) =
                    __floats2half2_rn(c[mi][ni][0], c[mi][ni][1]);
                *(__half2*)(Cw + (r0 + 8) * CWST + col) =
                    __floats2half2_rn(c[mi][ni][2], c[mi][ni][3]);
            }
        }
        __syncwarp();
        int n0 = t * 128 + wn * 64;
        #pragma unroll
        for (int p = 0; p < 8; p++) {
            int row = p * 4 + (lane >> 3);
            int gr = m0 + wm * 32 + row;
            if (gr < NN) {
                uint4 v = *(const uint4*)(Cw + row * CWST + (lane & 7) * 8);
                *(uint4*)(g_y + (size_t)gr * ystride + n0 + (lane & 7) * 8) = v;
            }
        }
    }
}

// ---------------- gather for 64-wide layers (half2, dual accumulators) ------
template <bool RES, bool WF32>
__global__ void gather64_kernel(const float* __restrict__ bias,
                                const float* __restrict__ resid,
                                float* __restrict__ outF) {
    int warpId = (blockIdx.x * blockDim.x + threadIdx.x) >> 5;
    int lane = threadIdx.x & 31;
    if (warpId >= NN) return;
    int i = warpId;
    int e0 = g_rowp[i], e1 = g_rowp[i + 1];
    float2 accA = make_float2(0.f, 0.f);
    float2 accB = make_float2(0.f, 0.f);
    int e = e0;
    for (; e + 1 < e1; e += 2) {
        uint4 ed0 = __ldg(&g_ed[e]);
        uint4 ed1 = __ldg(&g_ed[e + 1]);
        {
            uint32_t jk = ed0.x;
            int j = jk & 0xFFFFF, kb = (jk >> 20) & 63;
            float w0 = __uint_as_float(ed0.y);
            float w1 = __uint_as_float(ed0.z);
            float w2 = __uint_as_float(ed0.w);
            float w3 = (float)(jk >> 31) - w0 - w1 - w2;
            const __half2* r = (const __half2*)(g_y + (size_t)j * YS1 + kb * 64 + 2 * lane);
            float2 f0 = __half22float2(__ldg(r));
            float2 f1 = __half22float2(__ldg(r + 32));
            float2 f2 = __half22float2(__ldg(r + 256));
            float2 f3 = __half22float2(__ldg(r + 288));
            accA.x += w0 * f0.x + w1 * f1.x + w2 * f2.x + w3 * f3.x;
            accA.y += w0 * f0.y + w1 * f1.y + w2 * f2.y + w3 * f3.y;
        }
        {
            uint32_t jk = ed1.x;
            int j = jk & 0xFFFFF, kb = (jk >> 20) & 63;
            float w0 = __uint_as_float(ed1.y);
            float w1 = __uint_as_float(ed1.z);
            float w2 = __uint_as_float(ed1.w);
            float w3 = (float)(jk >> 31) - w0 - w1 - w2;
            const __half2* r = (const __half2*)(g_y + (size_t)j * YS1 + kb * 64 + 2 * lane);
            float2 f0 = __half22float2(__ldg(r));
            float2 f1 = __half22float2(__ldg(r + 32));
            float2 f2 = __half22float2(__ldg(r + 256));
            float2 f3 = __half22float2(__ldg(r + 288));
            accB.x += w0 * f0.x + w1 * f1.x + w2 * f2.x + w3 * f3.x;
            accB.y += w0 * f0.y + w1 * f1.y + w2 * f2.y + w3 * f3.y;
        }
    }
    if (e < e1) {
        uint4 ed0 = __ldg(&g_ed[e]);
        uint32_t jk = ed0.x;
        int j = jk & 0xFFFFF, kb = (jk >> 20) & 63;
        float w0 = __uint_as_float(ed0.y);
        float w1 = __uint_as_float(ed0.z);
        float w2 = __uint_as_float(ed0.w);
        float w3 = (float)(jk >> 31) - w0 - w1 - w2;
        const __half2* r = (const __half2*)(g_y + (size_t)j * YS1 + kb * 64 + 2 * lane);
        float2 f0 = __half22float2(__ldg(r));
        float2 f1 = __half22float2(__ldg(r + 32));
        float2 f2 = __half22float2(__ldg(r + 256));
        float2 f3 = __half22float2(__ldg(r + 288));
        accA.x += w0 * f0.x + w1 * f1.x + w2 * f2.x + w3 * f3.x;
        accA.y += w0 * f0.y + w1 * f1.y + w2 * f2.y + w3 * f3.y;
    }
    float2 acc = make_float2(accA.x + accB.x, accA.y + accB.y);
    float2 s = __half22float2(*(const __half2*)(g_y + (size_t)i * YS1 + 4096 + 2 * lane));
    float2 bv = *(const float2*)(bias + 2 * lane);
    float2 o = make_float2(acc.x + s.x + bv.x, acc.y + s.y + bv.y);
    if (RES) {
        float2 rv = *(const float2*)(resid + (size_t)i * 64 + 2 * lane);
        o.x += rv.x; o.y += rv.y;
    }
    if (WF32)
        *(float2*)(outF + (size_t)i * 64 + 2 * lane) = o;
    *(__half2*)(g_ah + (size_t)i * 64 + 2 * lane) =
        __floats2half2_rn(fmaxf(o.x, 0.f), fmaxf(o.y, 0.f));
}

// ---------------- final gather (Cout = 2) + /128 ----------------------------
__global__ void gatherF_kernel(const float* __restrict__ cb3,
                               const float* __restrict__ fb3,
                               float* __restrict__ out) {
    int warpId = (blockIdx.x * blockDim.x + threadIdx.x) >> 5;
    int lane = threadIdx.x & 31;
    if (warpId >= NN) return;
    int i = warpId;
    int e0 = g_rowp[i], e1 = g_rowp[i + 1];
    float accx = 0.f, accy = 0.f;
    for (int e = e0 + lane; e < e1; e += 32) {
        uint4 ed = __ldg(&g_ed[e]);
        uint32_t jk = ed.x;
        int j = jk & 0xFFFFF, kb = (jk >> 20) & 63;
        float w0 = __uint_as_float(ed.y);
        float w1 = __uint_as_float(ed.z);
        float w2 = __uint_as_float(ed.w);
        float w3 = (float)(jk >> 31) - w0 - w1 - w2;
        const __half2* r = (const __half2*)(g_y + (size_t)j * YS3 + kb * 2);
        float2 f0 = __half22float2(__ldg(r));
        float2 f1 = __half22float2(__ldg(r + 1));
        float2 f2 = __half22float2(__ldg(r + 8));
        float2 f3 = __half22float2(__ldg(r + 9));
        accx += w0 * f0.x + w1 * f1.x + w2 * f2.x + w3 * f3.x;
        accy += w0 * f0.y + w1 * f1.y + w2 * f2.y + w3 * f3.y;
    }
    #pragma unroll
    for (int off = 16; off > 0; off >>= 1) {
        accx += __shfl_down_sync(0xFFFFFFFFu, accx, off);
        accy += __shfl_down_sync(0xFFFFFFFFu, accy, off);
    }
    if (lane == 0) {
        float2 ds = __half22float2(*(const __half2*)(g_y + (size_t)i * YS3 + 128));
        out[2 * i]     = (accx + ds.x + cb3[0] + fb3[0]) * (1.f / 128.f);
        out[2 * i + 1] = (accy + ds.y + cb3[1] + fb3[1]) * (1.f / 128.f);
    }
}

// ---------------- launch ----------------------------------------------------
extern "C" void kernel_launch(void* const* d_in, const int* in_sizes, int n_in,
                              void* d_out, int out_size) {
    const float* pos  = (const float*)d_in[0];
    const float* feat = (const float*)d_in[1];
    const int*   ei   = (const int*)d_in[2];
    const int*   ej   = (const int*)d_in[3];
    const float* cw0 = (const float*)d_in[4];
    const float* cb0 = (const float*)d_in[5];
    const float* fw0 = (const float*)d_in[6];
    const float* fb0 = (const float*)d_in[7];
    const float* cw1 = (const float*)d_in[8];
    const float* cb1 = (const float*)d_in[9];
    const float* fw1 = (const float*)d_in[10];
    const float* fb1 = (const float*)d_in[11];
    const float* cw2 = (const float*)d_in[12];
    const float* cb2 = (const float*)d_in[13];
    const float* fw2 = (const float*)d_in[14];
    const float* fb2 = (const float*)d_in[15];
    const float* cw3 = (const float*)d_in[16];
    const float* cb3 = (const float*)d_in[17];
    const float* fw3 = (const float*)d_in[18];
    const float* fb3 = (const float*)d_in[19];
    float* out = (float*)d_out;
    int E = in_sizes[2];

    cudaFuncSetAttribute(gemmA_kernel,
                         cudaFuncAttributeMaxDynamicSharedMemorySize, SMEMA);
    cudaFuncSetAttribute(gemmP_kernel,
                         cudaFuncAttributeMaxDynamicSharedMemorySize, PSMEM);

    float* aF;  cudaGetSymbolAddress((void**)&aF, g_ansF);
    __half* w1; cudaGetSymbolAddress((void**)&w1, g_wc1);
    __half* w2; cudaGetSymbolAddress((void**)&w2, g_wc2);
    __half* w3; cudaGetSymbolAddress((void**)&w3, g_wc3);
    float* b1;  cudaGetSymbolAddress((void**)&b1, g_bias1);
    float* b2;  cudaGetSymbolAddress((void**)&b2, g_bias2);

    // all weight packing + cnt zero in one launch
    packAll_kernel<<<(PACK_TOT + 255) / 256, 256>>>(
        cw0, fw0, cb0, fb0, cw1, fw1, cb1, fb1,
        cw2, fw2, cb2, fb2, cw3, fw3);

    // edge counting sort (single atomic pass)
    hist_kernel<<<(E + 255) / 256, 256>>>(ei, E);
    scan1_kernel<<<SCAN_B, 1024>>>();
    scan2_kernel<<<1, 64>>>();
    scan3_kernel<<<SCAN_B, 1024>>>();
    scatter_kernel<<<(E + 255) / 256, 256>>>(pos, ei, ej, E);

    // layer 0 (moment formulation)
    mom0_kernel<<<NN / 8, 256>>>(feat);
    gemmA_kernel<<<391, 256, SMEMA>>>();

    // layer 1
    gemmP_kernel<<<dim3(391, 3), 256, PSMEM>>>(w1, NPAD, 11, 33, YS1);
    gather64_kernel<false, true><<<(NN * 32 + 255) / 256, 256>>>(b1, nullptr, aF);

    // layer 2 (residual = ansF)
    gemmP_kernel<<<dim3(391, 3), 256, PSMEM>>>(w2, NPAD, 11, 33, YS1);
    gather64_kernel<true, false><<<(NN * 32 + 255) / 256, 256>>>(b2, aF, nullptr);

    // layer 3
    gemmP_kernel<<<dim3(391, 2), 256, PSMEM>>>(w3, 256, 1, 2, YS3);
    gatherF_kernel<<<(NN * 32 + 255) / 256, 256>>>(cb3, fb3, out);
}